// round 2
// baseline (speedup 1.0000x reference)
#include <cuda_runtime.h>
#include <math.h>

#define Bsz 256
#define Tn  256
#define In  128
#define Hn  512

// Scratch (allocation-free rule: __device__ globals)
__device__ float g_xs[(size_t)Tn * Bsz * Hn];   // [T][B][H] precomputed input projections + biases
__device__ float g_h[2][Bsz * Hn];              // ping-pong hidden state

// ---------------------------------------------------------------------------
// Zero initial hidden state
// ---------------------------------------------------------------------------
__global__ void init_h_kernel() {
    int i = blockIdx.x * blockDim.x + threadIdx.x;
    if (i < Bsz * Hn) g_h[0][i] = 0.0f;
}

// ---------------------------------------------------------------------------
// xs[t*B+b][h] = sum_i x[b][t][i] * W_ih[h][i] + b_ih[h] + b_hh[h]
// Tiled GEMM: 32x32 tile, 256 threads, 2x2 register blocking, K-chunk 32
// ---------------------------------------------------------------------------
__global__ void xs_kernel(const float* __restrict__ x,
                          const float* __restrict__ W_ih,
                          const float* __restrict__ b_ih,
                          const float* __restrict__ b_hh) {
    __shared__ float As[32][33];
    __shared__ float Ws[32][33];
    int tid = threadIdx.x;
    int tx = tid & 15, ty = tid >> 4;
    int m0 = blockIdx.y * 32;   // m = t*B + b (32 consecutive m share the same t)
    int h0 = blockIdx.x * 32;

    float acc00 = 0.f, acc01 = 0.f, acc10 = 0.f, acc11 = 0.f;

    for (int k0 = 0; k0 < In; k0 += 32) {
        #pragma unroll
        for (int i = 0; i < 4; i++) {
            int idx = tid + i * 256;
            int r = idx >> 5, c = idx & 31;
            int m = m0 + r;
            int t = m >> 8;      // m / B
            int b = m & 255;     // m % B
            As[r][c] = x[((size_t)b * Tn + t) * In + k0 + c];
            Ws[r][c] = W_ih[(h0 + r) * In + k0 + c];
        }
        __syncthreads();
        #pragma unroll
        for (int k = 0; k < 32; k++) {
            float a0 = As[ty * 2][k],     a1 = As[ty * 2 + 1][k];
            float w0 = Ws[tx * 2][k],     w1 = Ws[tx * 2 + 1][k];
            acc00 += a0 * w0; acc01 += a0 * w1;
            acc10 += a1 * w0; acc11 += a1 * w1;
        }
        __syncthreads();
    }

    int h_a = h0 + tx * 2, h_b = h_a + 1;
    float bias_a = b_ih[h_a] + b_hh[h_a];
    float bias_b = b_ih[h_b] + b_hh[h_b];
    size_t m_a = (size_t)(m0 + ty * 2) * Hn;
    size_t m_b = (size_t)(m0 + ty * 2 + 1) * Hn;
    g_xs[m_a + h_a] = acc00 + bias_a;
    g_xs[m_a + h_b] = acc01 + bias_b;
    g_xs[m_b + h_a] = acc10 + bias_a;
    g_xs[m_b + h_b] = acc11 + bias_b;
}

// ---------------------------------------------------------------------------
// One recurrence step: h_new[b][h] = tanh(xs[t][b][h] + sum_k h_prev[b][k]*W_hh[h][k])
// ---------------------------------------------------------------------------
__global__ void step_kernel(const float* __restrict__ W_hh, int t, int src) {
    const float* __restrict__ h_prev = g_h[src];
    float* __restrict__ h_new = g_h[src ^ 1];
    const float* __restrict__ xs_t = g_xs + (size_t)t * Bsz * Hn;

    __shared__ float Hs[32][33];
    __shared__ float Ws[32][33];
    int tid = threadIdx.x;
    int tx = tid & 15, ty = tid >> 4;
    int b0 = blockIdx.y * 32;
    int h0 = blockIdx.x * 32;

    float acc00 = 0.f, acc01 = 0.f, acc10 = 0.f, acc11 = 0.f;

    for (int k0 = 0; k0 < Hn; k0 += 32) {
        #pragma unroll
        for (int i = 0; i < 4; i++) {
            int idx = tid + i * 256;
            int r = idx >> 5, c = idx & 31;
            Hs[r][c] = h_prev[(b0 + r) * Hn + k0 + c];
            Ws[r][c] = W_hh[(h0 + r) * Hn + k0 + c];
        }
        __syncthreads();
        #pragma unroll
        for (int k = 0; k < 32; k++) {
            float hb0 = Hs[ty * 2][k],     hb1 = Hs[ty * 2 + 1][k];
            float w0  = Ws[tx * 2][k],     w1  = Ws[tx * 2 + 1][k];
            acc00 += hb0 * w0; acc01 += hb0 * w1;
            acc10 += hb1 * w0; acc11 += hb1 * w1;
        }
        __syncthreads();
    }

    int b_a = b0 + ty * 2, b_b = b_a + 1;
    int h_a = h0 + tx * 2, h_b = h_a + 1;
    h_new[b_a * Hn + h_a] = tanhf(acc00 + xs_t[b_a * Hn + h_a]);
    h_new[b_a * Hn + h_b] = tanhf(acc01 + xs_t[b_a * Hn + h_b]);
    h_new[b_b * Hn + h_a] = tanhf(acc10 + xs_t[b_b * Hn + h_a]);
    h_new[b_b * Hn + h_b] = tanhf(acc11 + xs_t[b_b * Hn + h_b]);
}

// ---------------------------------------------------------------------------
// out[b] = dot(h_final[b], fc_w) + fc_b[0]
// ---------------------------------------------------------------------------
__global__ void fc_kernel(const float* __restrict__ fc_w,
                          const float* __restrict__ fc_b,
                          float* __restrict__ out, int src) {
    const float* __restrict__ h = g_h[src];
    int b = blockIdx.x;
    float acc = 0.f;
    for (int k = threadIdx.x; k < Hn; k += 128)
        acc += h[b * Hn + k] * fc_w[k];
    __shared__ float s[128];
    s[threadIdx.x] = acc;
    __syncthreads();
    #pragma unroll
    for (int o = 64; o > 0; o >>= 1) {
        if (threadIdx.x < o) s[threadIdx.x] += s[threadIdx.x + o];
        __syncthreads();
    }
    if (threadIdx.x == 0) out[b] = s[0] + fc_b[0];
}

// ---------------------------------------------------------------------------
extern "C" void kernel_launch(void* const* d_in, const int* in_sizes, int n_in,
                              void* d_out, int out_size) {
    const float* x    = (const float*)d_in[0];
    const float* W_ih = (const float*)d_in[1];
    const float* W_hh = (const float*)d_in[2];
    const float* b_ih = (const float*)d_in[3];
    const float* b_hh = (const float*)d_in[4];
    const float* fc_w = (const float*)d_in[5];
    const float* fc_b = (const float*)d_in[6];
    float* out = (float*)d_out;

    init_h_kernel<<<(Bsz * Hn + 255) / 256, 256>>>();

    dim3 gx(Hn / 32, (Tn * Bsz) / 32);   // (16, 2048)
    xs_kernel<<<gx, 256>>>(x, W_ih, b_ih, b_hh);

    dim3 gs(Hn / 32, Bsz / 32);          // (16, 8) = 128 blocks
    int src = 0;
    for (int t = 0; t < Tn; t++) {
        step_kernel<<<gs, 256>>>(W_hh, t, src);
        src ^= 1;
    }

    fc_kernel<<<Bsz, 128>>>(fc_w, fc_b, out, src);
}

// round 4
// speedup vs baseline: 2.3635x; 2.3635x over previous
#include <cuda_runtime.h>
#include <cuda_bf16.h>
#include <math.h>
#include <stdint.h>

#define Bsz 256
#define Tn  256
#define In  128
#define Hn  512
#define NCTA 64

// ---------------- device scratch ----------------
__device__ float g_xs[(size_t)Tn * Bsz * Hn];
__device__ __nv_bfloat16 g_hhi[2][Bsz * Hn];   // ping-pong hidden hi
__device__ __nv_bfloat16 g_hlo[2][Bsz * Hn];   // ping-pong hidden lo
__device__ float g_hT[Bsz * Hn];
__device__ unsigned int g_bar;

// ---------------- helpers ----------------
__device__ __forceinline__ uint32_t smem_u32(const void* p) {
    uint32_t a;
    asm("{ .reg .u64 t; cvta.to.shared.u64 t, %1; cvt.u32.u64 %0, t; }" : "=r"(a) : "l"(p));
    return a;
}
__device__ __forceinline__ void cpa16(uint32_t dst, const void* src) {
    asm volatile("cp.async.cg.shared.global [%0], [%1], 16;" :: "r"(dst), "l"(src));
}
#define CP_COMMIT() asm volatile("cp.async.commit_group;" ::: "memory")
#define CP_WAIT(n)  asm volatile("cp.async.wait_group %0;" :: "n"(n) : "memory")

__device__ __forceinline__ void ldsm4(uint32_t r[4], uint32_t addr) {
    asm volatile("ldmatrix.sync.aligned.m8n8.x4.shared.b16 {%0,%1,%2,%3}, [%4];"
                 : "=r"(r[0]), "=r"(r[1]), "=r"(r[2]), "=r"(r[3]) : "r"(addr));
}
__device__ __forceinline__ void mma_bf16(float c[4], const uint32_t a[4], uint32_t b0, uint32_t b1) {
    asm volatile("mma.sync.aligned.m16n8k16.row.col.f32.bf16.bf16.f32 "
                 "{%0,%1,%2,%3},{%4,%5,%6,%7},{%8,%9},{%0,%1,%2,%3};"
                 : "+f"(c[0]), "+f"(c[1]), "+f"(c[2]), "+f"(c[3])
                 : "r"(a[0]), "r"(a[1]), "r"(a[2]), "r"(a[3]), "r"(b0), "r"(b1));
}

// ---------------- init ----------------
__global__ void init_kernel() {
    int i = blockIdx.x * blockDim.x + threadIdx.x;
    if (i == 0) g_bar = 0u;
    // zero both ping-pong h buffers (hi and lo): 2 * 131072 bf16 each = 65536 uint4 total
    uint4* p1 = (uint4*)g_hhi;
    uint4* p2 = (uint4*)g_hlo;
    if (i < 32768) { p1[i] = make_uint4(0,0,0,0); p2[i] = make_uint4(0,0,0,0); }
}

// ---------------- xs GEMM (proven) ----------------
__global__ void xs_kernel(const float* __restrict__ x, const float* __restrict__ W_ih,
                          const float* __restrict__ b_ih, const float* __restrict__ b_hh) {
    __shared__ float As[32][33];
    __shared__ float Ws[32][33];
    int tid = threadIdx.x, tx = tid & 15, ty = tid >> 4;
    int m0 = blockIdx.y * 32, h0 = blockIdx.x * 32;
    float a00 = 0.f, a01 = 0.f, a10 = 0.f, a11 = 0.f;
    for (int k0 = 0; k0 < In; k0 += 32) {
        #pragma unroll
        for (int i = 0; i < 4; i++) {
            int idx = tid + i * 256, r = idx >> 5, c = idx & 31;
            int m = m0 + r, t = m >> 8, b = m & 255;
            As[r][c] = x[((size_t)b * Tn + t) * In + k0 + c];
            Ws[r][c] = W_ih[(h0 + r) * In + k0 + c];
        }
        __syncthreads();
        #pragma unroll
        for (int k = 0; k < 32; k++) {
            float x0 = As[ty*2][k], x1 = As[ty*2+1][k];
            float w0 = Ws[tx*2][k], w1 = Ws[tx*2+1][k];
            a00 += x0*w0; a01 += x0*w1; a10 += x1*w0; a11 += x1*w1;
        }
        __syncthreads();
    }
    int ha = h0 + tx*2, hb = ha + 1;
    float ba = b_ih[ha] + b_hh[ha], bb = b_ih[hb] + b_hh[hb];
    size_t ma = (size_t)(m0 + ty*2) * Hn, mb = (size_t)(m0 + ty*2 + 1) * Hn;
    g_xs[ma + ha] = a00 + ba; g_xs[ma + hb] = a01 + bb;
    g_xs[mb + ha] = a10 + ba; g_xs[mb + hb] = a11 + bb;
}

// ---------------- persistent recurrence (mma.sync bf16 3-term split) ----------------
// SMEM (bytes): W hi [32 rows x 1040B], W lo, A(h) hi [64 x 1040], A lo
#define ROWB 1040                 // 512 bf16 * 2B + 16B pad (conflict-free LDSM)
#define OFF_WHI 0
#define OFF_WLO 33280
#define OFF_AHI 66560
#define OFF_ALO 133120
#define SMEM_BYTES 199680

__global__ __launch_bounds__(128, 1)
void rnn_persist(const float* __restrict__ W_hh) {
    extern __shared__ unsigned char smem[];
    const uint32_t sb = smem_u32(smem);
    const int tid = threadIdx.x;
    const int wid = tid >> 5, lane = tid & 31;
    const int cta_m = blockIdx.x >> 4;          // 0..3  -> m rows [cta_m*64, +64)
    const int cta_n = blockIdx.x & 15;          // 0..15 -> n cols [cta_n*32, +32)
    const int m0 = cta_m * 64, n0 = cta_n * 32;

    // --- load W tile (rows n0..n0+31, all k) as bf16 hi/lo, padded row-major ---
    for (int idx = tid; idx < 32 * 512; idx += 128) {
        int r = idx >> 9, k = idx & 511;
        float w = W_hh[(size_t)(n0 + r) * Hn + k];
        __nv_bfloat16 hi = __float2bfloat16(w);
        __nv_bfloat16 lo = __float2bfloat16(w - __bfloat162float(hi));
        *(__nv_bfloat16*)(smem + OFF_WHI + r * ROWB + k * 2) = hi;
        *(__nv_bfloat16*)(smem + OFF_WLO + r * ROWB + k * 2) = lo;
    }
    __syncthreads();

    // per-lane constants
    const int gq = lane >> 2, tq = lane & 3;
    const int r0 = m0 + wid * 16 + gq;          // global batch row (c0,c1)
    const int r1 = r0 + 8;                      // (c2,c3)
    // ldmatrix source addresses (per-lane), k-byte added in loop
    const int ja = lane >> 3, ra = lane & 7;
    const uint32_t a_row_off = (uint32_t)(wid * 16 + (ja & 1) * 8 + ra) * ROWB + (uint32_t)(ja >> 1) * 16;
    const uint32_t b_row_off0 = (uint32_t)((ja >> 1) * 8 + ra) * ROWB + (uint32_t)(ja & 1) * 16;        // ntiles 0,1
    const uint32_t b_row_off1 = (uint32_t)(16 + (ja >> 1) * 8 + ra) * ROWB + (uint32_t)(ja & 1) * 16;   // ntiles 2,3

    for (int t = 0; t < Tn; t++) {
        const int rb = t & 1, wb = rb ^ 1;
        const __nv_bfloat16* hh = g_hhi[rb];
        const __nv_bfloat16* hl = g_hlo[rb];

        // issue cp.async for both k-halves of this CTA's h rows (hi + lo)
        #pragma unroll
        for (int kc = 0; kc < 2; kc++) {
            for (int i = tid; i < 64 * 32; i += 128) {   // 64 rows x 32 chunks of 16B (512B = 256 bf16)
                int row = i >> 5, inner = i & 31;
                uint32_t so = (uint32_t)row * ROWB + (uint32_t)kc * 512 + (uint32_t)inner * 16;
                size_t go = (size_t)(m0 + row) * Hn + kc * 256 + inner * 8;
                cpa16(sb + OFF_AHI + so, hh + go);
                cpa16(sb + OFF_ALO + so, hl + go);
            }
            CP_COMMIT();
        }

        // prefetch xs into regs (independent of smem pipeline)
        const float* xs_t = g_xs + (size_t)t * (Bsz * Hn);
        float2 xv[8];
        #pragma unroll
        for (int n4 = 0; n4 < 4; n4++) {
            int col = n0 + n4 * 8 + tq * 2;
            xv[n4*2]   = *(const float2*)(xs_t + (size_t)r0 * Hn + col);
            xv[n4*2+1] = *(const float2*)(xs_t + (size_t)r1 * Hn + col);
        }

        float c[4][4];
        #pragma unroll
        for (int i = 0; i < 4; i++)
            #pragma unroll
            for (int j = 0; j < 4; j++) c[i][j] = 0.f;

        #pragma unroll
        for (int kc = 0; kc < 2; kc++) {
            if (kc == 0) { CP_WAIT(1); } else { CP_WAIT(0); }
            __syncthreads();
            #pragma unroll 4
            for (int ks = 0; ks < 16; ks++) {
                uint32_t kb = (uint32_t)(kc * 16 + ks) * 32;   // byte offset of this k16 within row
                uint32_t ahi[4], alo[4], bhi0[4], blo0[4], bhi1[4], blo1[4];
                ldsm4(ahi, sb + OFF_AHI + a_row_off + kb);
                ldsm4(alo, sb + OFF_ALO + a_row_off + kb);
                ldsm4(bhi0, sb + OFF_WHI + b_row_off0 + kb);
                ldsm4(bhi1, sb + OFF_WHI + b_row_off1 + kb);
                ldsm4(blo0, sb + OFF_WLO + b_row_off0 + kb);
                ldsm4(blo1, sb + OFF_WLO + b_row_off1 + kb);
                // ntile0
                mma_bf16(c[0], ahi, bhi0[0], bhi0[1]);
                mma_bf16(c[0], ahi, blo0[0], blo0[1]);
                mma_bf16(c[0], alo, bhi0[0], bhi0[1]);
                // ntile1
                mma_bf16(c[1], ahi, bhi0[2], bhi0[3]);
                mma_bf16(c[1], ahi, blo0[2], blo0[3]);
                mma_bf16(c[1], alo, bhi0[2], bhi0[3]);
                // ntile2
                mma_bf16(c[2], ahi, bhi1[0], bhi1[1]);
                mma_bf16(c[2], ahi, blo1[0], blo1[1]);
                mma_bf16(c[2], alo, bhi1[0], bhi1[1]);
                // ntile3
                mma_bf16(c[3], ahi, bhi1[2], bhi1[3]);
                mma_bf16(c[3], ahi, blo1[2], blo1[3]);
                mma_bf16(c[3], alo, bhi1[2], bhi1[3]);
            }
            if (kc == 0) __syncthreads();   // all warps done with half0 before reuse? (regions disjoint, but cheap safety)
        }

        // epilogue: tanh(c + xs), write bf16 hi/lo to ping-pong buffers
        __nv_bfloat16* ohh = g_hhi[wb];
        __nv_bfloat16* ohl = g_hlo[wb];
        #pragma unroll
        for (int n4 = 0; n4 < 4; n4++) {
            int col = n0 + n4 * 8 + tq * 2;
            #pragma unroll
            for (int hfl = 0; hfl < 2; hfl++) {
                int row = hfl ? r1 : r0;
                float s0 = tanhf(c[n4][hfl*2]   + (hfl ? xv[n4*2+1].x : xv[n4*2].x));
                float s1 = tanhf(c[n4][hfl*2+1] + (hfl ? xv[n4*2+1].y : xv[n4*2].y));
                __nv_bfloat16 h0 = __float2bfloat16(s0);
                __nv_bfloat16 h1 = __float2bfloat16(s1);
                uint32_t wh = (uint32_t)__bfloat16_as_ushort(h0) | ((uint32_t)__bfloat16_as_ushort(h1) << 16);
                uint32_t wl = (uint32_t)__bfloat16_as_ushort(__float2bfloat16(s0 - __bfloat162float(h0)))
                            | ((uint32_t)__bfloat16_as_ushort(__float2bfloat16(s1 - __bfloat162float(h1))) << 16);
                size_t off = (size_t)row * Hn + col;
                *(uint32_t*)(ohh + off) = wh;
                *(uint32_t*)(ohl + off) = wl;
                if (t == Tn - 1) *(float2*)(g_hT + off) = make_float2(s0, s1);
            }
        }

        // grid barrier (monotonic counter; 64 CTAs single wave)
        __threadfence();
        __syncthreads();
        if (tid == 0) {
            unsigned int target = (unsigned int)(t + 1) * NCTA;
            atomicAdd(&g_bar, 1u);
            while (*((volatile unsigned int*)&g_bar) < target) { }
            __threadfence();
        }
        __syncthreads();
    }
}

// ---------------- final FC ----------------
__global__ void fc_kernel(const float* __restrict__ fc_w, const float* __restrict__ fc_b,
                          float* __restrict__ out) {
    int b = blockIdx.x;
    float acc = 0.f;
    for (int k = threadIdx.x; k < Hn; k += 128)
        acc += g_hT[b * Hn + k] * fc_w[k];
    __shared__ float s[128];
    s[threadIdx.x] = acc;
    __syncthreads();
    #pragma unroll
    for (int o = 64; o > 0; o >>= 1) {
        if (threadIdx.x < o) s[threadIdx.x] += s[threadIdx.x + o];
        __syncthreads();
    }
    if (threadIdx.x == 0) out[b] = s[0] + fc_b[0];
}

extern "C" void kernel_launch(void* const* d_in, const int* in_sizes, int n_in,
                              void* d_out, int out_size) {
    const float* x    = (const float*)d_in[0];
    const float* W_ih = (const float*)d_in[1];
    const float* W_hh = (const float*)d_in[2];
    const float* b_ih = (const float*)d_in[3];
    const float* b_hh = (const float*)d_in[4];
    const float* fc_w = (const float*)d_in[5];
    const float* fc_b = (const float*)d_in[6];
    float* out = (float*)d_out;

    cudaFuncSetAttribute(rnn_persist, cudaFuncAttributeMaxDynamicSharedMemorySize, SMEM_BYTES);

    init_kernel<<<256, 256>>>();
    dim3 gx(Hn / 32, (Tn * Bsz) / 32);
    xs_kernel<<<gx, 256>>>(x, W_ih, b_ih, b_hh);
    rnn_persist<<<NCTA, 128, SMEM_BYTES>>>(W_hh);
    fc_kernel<<<Bsz, 128>>>(fc_w, fc_b, out);
}

// round 5
// speedup vs baseline: 3.8169x; 1.6149x over previous
#include <cuda_runtime.h>
#include <cuda_bf16.h>
#include <math.h>
#include <stdint.h>

#define Bsz 256
#define Tn  256
#define In  128
#define Hn  512
#define NCTA 128

// ---------------- device scratch ----------------
__device__ float g_xs[(size_t)Tn * Bsz * Hn];
__device__ __nv_bfloat16 g_hhi[2][Bsz * Hn];
__device__ __nv_bfloat16 g_hlo[2][Bsz * Hn];
__device__ float g_hT[Bsz * Hn];
__device__ unsigned int g_bar;

// ---------------- helpers ----------------
__device__ __forceinline__ uint32_t smem_u32(const void* p) {
    uint32_t a;
    asm("{ .reg .u64 t; cvta.to.shared.u64 t, %1; cvt.u32.u64 %0, t; }" : "=r"(a) : "l"(p));
    return a;
}
__device__ __forceinline__ void cpa16(uint32_t dst, const void* src) {
    asm volatile("cp.async.cg.shared.global [%0], [%1], 16;" :: "r"(dst), "l"(src));
}
#define CP_COMMIT() asm volatile("cp.async.commit_group;" ::: "memory")
#define CP_WAIT(n)  asm volatile("cp.async.wait_group %0;" :: "n"(n) : "memory")

__device__ __forceinline__ void ldsm4(uint32_t r[4], uint32_t addr) {
    asm volatile("ldmatrix.sync.aligned.m8n8.x4.shared.b16 {%0,%1,%2,%3}, [%4];"
                 : "=r"(r[0]), "=r"(r[1]), "=r"(r[2]), "=r"(r[3]) : "r"(addr));
}
__device__ __forceinline__ void mma_bf16(float c[4], const uint32_t a[4], uint32_t b0, uint32_t b1) {
    asm volatile("mma.sync.aligned.m16n8k16.row.col.f32.bf16.bf16.f32 "
                 "{%0,%1,%2,%3},{%4,%5,%6,%7},{%8,%9},{%0,%1,%2,%3};"
                 : "+f"(c[0]), "+f"(c[1]), "+f"(c[2]), "+f"(c[3])
                 : "r"(a[0]), "r"(a[1]), "r"(a[2]), "r"(a[3]), "r"(b0), "r"(b1));
}
__device__ __forceinline__ void bar_arrive() {
    asm volatile("red.add.release.gpu.u32 [%0], 1;" :: "l"(&g_bar) : "memory");
}
__device__ __forceinline__ uint32_t bar_ld() {
    uint32_t v;
    asm volatile("ld.acquire.gpu.u32 %0, [%1];" : "=r"(v) : "l"(&g_bar) : "memory");
    return v;
}
__device__ __forceinline__ uint32_t pack_bf16x2(float a, float b) {
    __nv_bfloat16 ha = __float2bfloat16(a), hb = __float2bfloat16(b);
    return (uint32_t)__bfloat16_as_ushort(ha) | ((uint32_t)__bfloat16_as_ushort(hb) << 16);
}

// ---------------- init ----------------
__global__ void init_kernel() {
    int i = blockIdx.x * blockDim.x + threadIdx.x;
    if (i == 0) g_bar = 0u;
    uint4* p1 = (uint4*)g_hhi;
    uint4* p2 = (uint4*)g_hlo;
    if (i < 32768) { p1[i] = make_uint4(0,0,0,0); p2[i] = make_uint4(0,0,0,0); }
}

// ---------------- xs GEMM via mma.sync (M=65536,N=512,K=128) ----------------
// CTA: 256 threads (8 warps, 4x2 of m32n32), tile m128 x n64, full K=128 in smem.
#define XROWB 272   // 128 bf16 * 2 + 16B pad
#define XS_AHI 0
#define XS_ALO 34816
#define XS_WHI 69632
#define XS_WLO 87040
#define SMEM_XS 104448

__global__ __launch_bounds__(256, 1)
void xs_mma_kernel(const float* __restrict__ x, const float* __restrict__ W_ih,
                   const float* __restrict__ b_ih, const float* __restrict__ b_hh) {
    extern __shared__ unsigned char smem[];
    const uint32_t sb = smem_u32(smem);
    const int tid = threadIdx.x;
    const int wid = tid >> 5, lane = tid & 31;
    const int m0 = blockIdx.y * 128;        // 512 blocks in y
    const int n0 = blockIdx.x * 64;         // 8 blocks in x
    const int tt = m0 >> 8;                 // constant t for this block
    const int b0 = m0 & 255;

    // Load A tile: 128 rows x 128 k, fp32 -> bf16 hi/lo. 2 threads per row.
    {
        int r = tid >> 1, seg = (tid & 1) * 64;   // 64 floats per thread
        const float4* src = (const float4*)(x + ((size_t)(b0 + r) * Tn + tt) * In + seg);
        uint32_t dhi = sb + XS_AHI + r * XROWB + seg * 2;
        uint32_t dlo = sb + XS_ALO + r * XROWB + seg * 2;
        #pragma unroll
        for (int q = 0; q < 16; q++) {
            float4 v = src[q];
            __nv_bfloat16 h0 = __float2bfloat16(v.x), h1 = __float2bfloat16(v.y);
            __nv_bfloat16 h2 = __float2bfloat16(v.z), h3 = __float2bfloat16(v.w);
            uint32_t hi0 = (uint32_t)__bfloat16_as_ushort(h0) | ((uint32_t)__bfloat16_as_ushort(h1) << 16);
            uint32_t hi1 = (uint32_t)__bfloat16_as_ushort(h2) | ((uint32_t)__bfloat16_as_ushort(h3) << 16);
            uint32_t lo0 = pack_bf16x2(v.x - __bfloat162float(h0), v.y - __bfloat162float(h1));
            uint32_t lo1 = pack_bf16x2(v.z - __bfloat162float(h2), v.w - __bfloat162float(h3));
            asm volatile("st.shared.v2.b32 [%0], {%1,%2};" :: "r"(dhi + q * 8), "r"(hi0), "r"(hi1));
            asm volatile("st.shared.v2.b32 [%0], {%1,%2};" :: "r"(dlo + q * 8), "r"(lo0), "r"(lo1));
        }
    }
    // Load W tile: 64 rows x 128 k. 4 threads per row.
    {
        int r = tid >> 2, seg = (tid & 3) * 32;
        const float4* src = (const float4*)(W_ih + (size_t)(n0 + r) * In + seg);
        uint32_t dhi = sb + XS_WHI + r * XROWB + seg * 2;
        uint32_t dlo = sb + XS_WLO + r * XROWB + seg * 2;
        #pragma unroll
        for (int q = 0; q < 8; q++) {
            float4 v = src[q];
            __nv_bfloat16 h0 = __float2bfloat16(v.x), h1 = __float2bfloat16(v.y);
            __nv_bfloat16 h2 = __float2bfloat16(v.z), h3 = __float2bfloat16(v.w);
            uint32_t hi0 = (uint32_t)__bfloat16_as_ushort(h0) | ((uint32_t)__bfloat16_as_ushort(h1) << 16);
            uint32_t hi1 = (uint32_t)__bfloat16_as_ushort(h2) | ((uint32_t)__bfloat16_as_ushort(h3) << 16);
            uint32_t lo0 = pack_bf16x2(v.x - __bfloat162float(h0), v.y - __bfloat162float(h1));
            uint32_t lo1 = pack_bf16x2(v.z - __bfloat162float(h2), v.w - __bfloat162float(h3));
            asm volatile("st.shared.v2.b32 [%0], {%1,%2};" :: "r"(dhi + q * 8), "r"(hi0), "r"(hi1));
            asm volatile("st.shared.v2.b32 [%0], {%1,%2};" :: "r"(dlo + q * 8), "r"(lo0), "r"(lo1));
        }
    }
    __syncthreads();

    const int wm = wid & 3, wn = wid >> 2;   // warp m32n32 at (wm*32, wn*32)
    const int ja = lane >> 3, ra = lane & 7;
    const int gq = lane >> 2, tq = lane & 3;

    uint32_t a_off[2], w_off[2];
    #pragma unroll
    for (int mt = 0; mt < 2; mt++)
        a_off[mt] = (uint32_t)(wm * 32 + mt * 16 + (ja & 1) * 8 + ra) * XROWB + (uint32_t)(ja >> 1) * 16;
    #pragma unroll
    for (int np = 0; np < 2; np++)
        w_off[np] = (uint32_t)(wn * 32 + np * 16 + (ja >> 1) * 8 + ra) * XROWB + (uint32_t)(ja & 1) * 16;

    float c[2][4][4];
    #pragma unroll
    for (int i = 0; i < 2; i++)
        #pragma unroll
        for (int j = 0; j < 4; j++)
            #pragma unroll
            for (int q = 0; q < 4; q++) c[i][j][q] = 0.f;

    #pragma unroll
    for (int ks = 0; ks < 8; ks++) {
        uint32_t kb = (uint32_t)ks * 32;
        uint32_t ahi[2][4], alo[2][4], whi[2][4], wlo[2][4];
        #pragma unroll
        for (int mt = 0; mt < 2; mt++) {
            ldsm4(ahi[mt], sb + XS_AHI + a_off[mt] + kb);
            ldsm4(alo[mt], sb + XS_ALO + a_off[mt] + kb);
        }
        #pragma unroll
        for (int np = 0; np < 2; np++) {
            ldsm4(whi[np], sb + XS_WHI + w_off[np] + kb);
            ldsm4(wlo[np], sb + XS_WLO + w_off[np] + kb);
        }
        #pragma unroll
        for (int mt = 0; mt < 2; mt++)
            #pragma unroll
            for (int nt = 0; nt < 4; nt++) {
                int np = nt >> 1, h = (nt & 1) * 2;
                mma_bf16(c[mt][nt], ahi[mt], whi[np][h], whi[np][h + 1]);
                mma_bf16(c[mt][nt], ahi[mt], wlo[np][h], wlo[np][h + 1]);
                mma_bf16(c[mt][nt], alo[mt], whi[np][h], whi[np][h + 1]);
            }
    }

    // epilogue: + (b_ih + b_hh), write fp32
    #pragma unroll
    for (int nt = 0; nt < 4; nt++) {
        int col = n0 + wn * 32 + nt * 8 + tq * 2;
        float ba = b_ih[col] + b_hh[col];
        float bb = b_ih[col + 1] + b_hh[col + 1];
        #pragma unroll
        for (int mt = 0; mt < 2; mt++) {
            int row = m0 + wm * 32 + mt * 16 + gq;
            *(float2*)(g_xs + (size_t)row * Hn + col)       = make_float2(c[mt][nt][0] + ba, c[mt][nt][1] + bb);
            *(float2*)(g_xs + (size_t)(row + 8) * Hn + col) = make_float2(c[mt][nt][2] + ba, c[mt][nt][3] + bb);
        }
    }
}

// ---------------- persistent recurrence: CTA m32n32, warp m16n16, 128 CTAs ----------------
#define ROWB 1040
#define OFF_WHI 0
#define OFF_WLO 33280
#define OFF_AHI 66560
#define OFF_ALO 99840
#define SMEM_RP 133120

__global__ __launch_bounds__(128, 1)
void rnn_persist(const float* __restrict__ W_hh) {
    extern __shared__ unsigned char smem[];
    const uint32_t sb = smem_u32(smem);
    const int tid = threadIdx.x;
    const int wid = tid >> 5, lane = tid & 31;
    const int cta_m = blockIdx.x >> 4;          // 0..7  -> m rows [cta_m*32, +32)
    const int cta_n = blockIdx.x & 15;          // 0..15 -> n cols [cta_n*32, +32)
    const int m0 = cta_m * 32, n0 = cta_n * 32;

    // W tile: rows [n0, +32), all k, hi/lo
    for (int idx = tid; idx < 32 * 512; idx += 128) {
        int r = idx >> 9, k = idx & 511;
        float w = W_hh[(size_t)(n0 + r) * Hn + k];
        __nv_bfloat16 hi = __float2bfloat16(w);
        __nv_bfloat16 lo = __float2bfloat16(w - __bfloat162float(hi));
        *(__nv_bfloat16*)(smem + OFF_WHI + r * ROWB + k * 2) = hi;
        *(__nv_bfloat16*)(smem + OFF_WLO + r * ROWB + k * 2) = lo;
    }
    __syncthreads();

    const int wm = wid & 1, wn = wid >> 1;      // warp m16n16 at (wm*16, wn*16)
    const int gq = lane >> 2, tq = lane & 3;
    const int ja = lane >> 3, ra = lane & 7;
    const int r0 = m0 + wm * 16 + gq;
    const int r1 = r0 + 8;
    const uint32_t a_off = (uint32_t)(wm * 16 + (ja & 1) * 8 + ra) * ROWB + (uint32_t)(ja >> 1) * 16;
    const uint32_t b_off = (uint32_t)(wn * 16 + (ja >> 1) * 8 + ra) * ROWB + (uint32_t)(ja & 1) * 16;
    const int col0 = n0 + wn * 16 + tq * 2;     // nt0 col ; nt1 = col0+8

    for (int t = 0; t < Tn; t++) {
        const int rb = t & 1, wb = rb ^ 1;
        const __nv_bfloat16* hh = g_hhi[rb];
        const __nv_bfloat16* hl = g_hlo[rb];

        // cp.async A rows (m0..m0+31), two k-halves
        #pragma unroll
        for (int kc = 0; kc < 2; kc++) {
            for (int i = tid; i < 1024; i += 128) {
                int row = i >> 5, inner = i & 31;
                uint32_t so = (uint32_t)row * ROWB + (uint32_t)kc * 512 + (uint32_t)inner * 16;
                size_t go = (size_t)(m0 + row) * Hn + kc * 256 + inner * 8;
                cpa16(sb + OFF_AHI + so, hh + go);
                cpa16(sb + OFF_ALO + so, hl + go);
            }
            CP_COMMIT();
        }

        // xs prefetch
        const float* xs_t = g_xs + (size_t)t * (Bsz * Hn);
        float2 xv[2][2];
        #pragma unroll
        for (int nt = 0; nt < 2; nt++) {
            xv[nt][0] = *(const float2*)(xs_t + (size_t)r0 * Hn + col0 + nt * 8);
            xv[nt][1] = *(const float2*)(xs_t + (size_t)r1 * Hn + col0 + nt * 8);
        }

        float c[2][4];
        #pragma unroll
        for (int i = 0; i < 2; i++)
            #pragma unroll
            for (int j = 0; j < 4; j++) c[i][j] = 0.f;

        #pragma unroll
        for (int kc = 0; kc < 2; kc++) {
            if (kc == 0) { CP_WAIT(1); } else { CP_WAIT(0); }
            __syncthreads();
            #pragma unroll 4
            for (int ks = 0; ks < 16; ks++) {
                uint32_t kb = (uint32_t)(kc * 16 + ks) * 32;
                uint32_t ahi[4], alo[4], bhi[4], blo[4];
                ldsm4(ahi, sb + OFF_AHI + a_off + kb);
                ldsm4(alo, sb + OFF_ALO + a_off + kb);
                ldsm4(bhi, sb + OFF_WHI + b_off + kb);
                ldsm4(blo, sb + OFF_WLO + b_off + kb);
                mma_bf16(c[0], ahi, bhi[0], bhi[1]);
                mma_bf16(c[0], ahi, blo[0], blo[1]);
                mma_bf16(c[0], alo, bhi[0], bhi[1]);
                mma_bf16(c[1], ahi, bhi[2], bhi[3]);
                mma_bf16(c[1], ahi, blo[2], blo[3]);
                mma_bf16(c[1], alo, bhi[2], bhi[3]);
            }
            if (kc == 0) __syncthreads();
        }

        // epilogue
        __nv_bfloat16* ohh = g_hhi[wb];
        __nv_bfloat16* ohl = g_hlo[wb];
        #pragma unroll
        for (int nt = 0; nt < 2; nt++) {
            int col = col0 + nt * 8;
            #pragma unroll
            for (int hf = 0; hf < 2; hf++) {
                int row = hf ? r1 : r0;
                float s0 = tanhf(c[nt][hf * 2]     + xv[nt][hf].x);
                float s1 = tanhf(c[nt][hf * 2 + 1] + xv[nt][hf].y);
                __nv_bfloat16 h0 = __float2bfloat16(s0);
                __nv_bfloat16 h1 = __float2bfloat16(s1);
                uint32_t wh = (uint32_t)__bfloat16_as_ushort(h0) | ((uint32_t)__bfloat16_as_ushort(h1) << 16);
                uint32_t wl = pack_bf16x2(s0 - __bfloat162float(h0), s1 - __bfloat162float(h1));
                size_t off = (size_t)row * Hn + col;
                *(uint32_t*)(ohh + off) = wh;
                *(uint32_t*)(ohl + off) = wl;
                if (t == Tn - 1) *(float2*)(g_hT + off) = make_float2(s0, s1);
            }
        }

        // grid barrier: release-arrive + acquire-poll (128 CTAs, single wave)
        __syncthreads();
        if (tid == 0) {
            bar_arrive();
            unsigned int target = (unsigned int)(t + 1) * NCTA;
            while (bar_ld() < target) { }
        }
        __syncthreads();
    }
}

// ---------------- final FC ----------------
__global__ void fc_kernel(const float* __restrict__ fc_w, const float* __restrict__ fc_b,
                          float* __restrict__ out) {
    int b = blockIdx.x;
    float acc = 0.f;
    for (int k = threadIdx.x; k < Hn; k += 128)
        acc += g_hT[b * Hn + k] * fc_w[k];
    __shared__ float s[128];
    s[threadIdx.x] = acc;
    __syncthreads();
    #pragma unroll
    for (int o = 64; o > 0; o >>= 1) {
        if (threadIdx.x < o) s[threadIdx.x] += s[threadIdx.x + o];
        __syncthreads();
    }
    if (threadIdx.x == 0) out[b] = s[0] + fc_b[0];
}

extern "C" void kernel_launch(void* const* d_in, const int* in_sizes, int n_in,
                              void* d_out, int out_size) {
    const float* x    = (const float*)d_in[0];
    const float* W_ih = (const float*)d_in[1];
    const float* W_hh = (const float*)d_in[2];
    const float* b_ih = (const float*)d_in[3];
    const float* b_hh = (const float*)d_in[4];
    const float* fc_w = (const float*)d_in[5];
    const float* fc_b = (const float*)d_in[6];
    float* out = (float*)d_out;

    cudaFuncSetAttribute(xs_mma_kernel, cudaFuncAttributeMaxDynamicSharedMemorySize, SMEM_XS);
    cudaFuncSetAttribute(rnn_persist, cudaFuncAttributeMaxDynamicSharedMemorySize, SMEM_RP);

    init_kernel<<<256, 256>>>();
    dim3 gx(Hn / 64, (Tn * Bsz) / 128);   // (8, 512)
    xs_mma_kernel<<<gx, 256, SMEM_XS>>>(x, W_ih, b_ih, b_hh);
    rnn_persist<<<NCTA, 128, SMEM_RP>>>(W_hh);
    fc_kernel<<<Bsz, 128>>>(fc_w, fc_b, out);
}

// round 6
// speedup vs baseline: 3.8819x; 1.0170x over previous
#include <cuda_runtime.h>
#include <cuda_bf16.h>
#include <math.h>
#include <stdint.h>

#define Bsz 256
#define Tn  256
#define In  128
#define Hn  512
#define NCTA 128
#define GROUP_SZ 16   // CTAs per m-group (one per n-tile)

// ---------------- device scratch ----------------
__device__ float g_xs[(size_t)Tn * Bsz * Hn];
__device__ __nv_bfloat16 g_hhi[2][Bsz * Hn];
__device__ __nv_bfloat16 g_hlo[2][Bsz * Hn];
__device__ float g_hT[Bsz * Hn];
__device__ unsigned int g_bar8[8 * 32];   // one counter per m-group, padded 128B

// ---------------- helpers ----------------
__device__ __forceinline__ uint32_t smem_u32(const void* p) {
    uint32_t a;
    asm("{ .reg .u64 t; cvta.to.shared.u64 t, %1; cvt.u32.u64 %0, t; }" : "=r"(a) : "l"(p));
    return a;
}
__device__ __forceinline__ void cpa16(uint32_t dst, const void* src) {
    asm volatile("cp.async.cg.shared.global [%0], [%1], 16;" :: "r"(dst), "l"(src));
}
#define CP_COMMIT() asm volatile("cp.async.commit_group;" ::: "memory")
#define CP_WAIT(n)  asm volatile("cp.async.wait_group %0;" :: "n"(n) : "memory")

__device__ __forceinline__ void ldsm4(uint32_t r[4], uint32_t addr) {
    asm volatile("ldmatrix.sync.aligned.m8n8.x4.shared.b16 {%0,%1,%2,%3}, [%4];"
                 : "=r"(r[0]), "=r"(r[1]), "=r"(r[2]), "=r"(r[3]) : "r"(addr));
}
__device__ __forceinline__ void mma_bf16(float c[4], const uint32_t a[4], uint32_t b0, uint32_t b1) {
    asm volatile("mma.sync.aligned.m16n8k16.row.col.f32.bf16.bf16.f32 "
                 "{%0,%1,%2,%3},{%4,%5,%6,%7},{%8,%9},{%0,%1,%2,%3};"
                 : "+f"(c[0]), "+f"(c[1]), "+f"(c[2]), "+f"(c[3])
                 : "r"(a[0]), "r"(a[1]), "r"(a[2]), "r"(a[3]), "r"(b0), "r"(b1));
}
__device__ __forceinline__ void bar_arrive(unsigned int* p) {
    asm volatile("red.add.release.gpu.u32 [%0], 1;" :: "l"(p) : "memory");
}
__device__ __forceinline__ uint32_t bar_ld(unsigned int* p) {
    uint32_t v;
    asm volatile("ld.acquire.gpu.u32 %0, [%1];" : "=r"(v) : "l"(p) : "memory");
    return v;
}
__device__ __forceinline__ uint32_t pack_bf16x2(float a, float b) {
    __nv_bfloat16 ha = __float2bfloat16(a), hb = __float2bfloat16(b);
    return (uint32_t)__bfloat16_as_ushort(ha) | ((uint32_t)__bfloat16_as_ushort(hb) << 16);
}

// ---------------- init ----------------
__global__ void init_kernel() {
    int i = blockIdx.x * blockDim.x + threadIdx.x;
    if (i < 8 * 32) g_bar8[i] = 0u;
    uint4* p1 = (uint4*)g_hhi;
    uint4* p2 = (uint4*)g_hlo;
    if (i < 32768) { p1[i] = make_uint4(0,0,0,0); p2[i] = make_uint4(0,0,0,0); }
}

// ---------------- xs GEMM via mma.sync (M=65536,N=512,K=128) ----------------
#define XROWB 272
#define XS_AHI 0
#define XS_ALO 34816
#define XS_WHI 69632
#define XS_WLO 87040
#define SMEM_XS 104448
#define XSTG 272        // staging row stride bytes (17 uint4, conflict-free)

__global__ __launch_bounds__(256, 1)
void xs_mma_kernel(const float* __restrict__ x, const float* __restrict__ W_ih,
                   const float* __restrict__ b_ih, const float* __restrict__ b_hh) {
    extern __shared__ unsigned char smem[];
    const uint32_t sb = smem_u32(smem);
    const int tid = threadIdx.x;
    const int wid = tid >> 5, lane = tid & 31;
    const int m0 = blockIdx.y * 128;
    const int n0 = blockIdx.x * 64;
    const int tt = m0 >> 8;
    const int b0 = m0 & 255;

    // A tile 128x128 fp32 -> bf16 hi/lo
    {
        int r = tid >> 1, seg = (tid & 1) * 64;
        const float4* src = (const float4*)(x + ((size_t)(b0 + r) * Tn + tt) * In + seg);
        uint32_t dhi = sb + XS_AHI + r * XROWB + seg * 2;
        uint32_t dlo = sb + XS_ALO + r * XROWB + seg * 2;
        #pragma unroll
        for (int q = 0; q < 16; q++) {
            float4 v = src[q];
            __nv_bfloat16 h0 = __float2bfloat16(v.x), h1 = __float2bfloat16(v.y);
            __nv_bfloat16 h2 = __float2bfloat16(v.z), h3 = __float2bfloat16(v.w);
            uint32_t hi0 = (uint32_t)__bfloat16_as_ushort(h0) | ((uint32_t)__bfloat16_as_ushort(h1) << 16);
            uint32_t hi1 = (uint32_t)__bfloat16_as_ushort(h2) | ((uint32_t)__bfloat16_as_ushort(h3) << 16);
            uint32_t lo0 = pack_bf16x2(v.x - __bfloat162float(h0), v.y - __bfloat162float(h1));
            uint32_t lo1 = pack_bf16x2(v.z - __bfloat162float(h2), v.w - __bfloat162float(h3));
            asm volatile("st.shared.v2.b32 [%0], {%1,%2};" :: "r"(dhi + q * 8), "r"(hi0), "r"(hi1));
            asm volatile("st.shared.v2.b32 [%0], {%1,%2};" :: "r"(dlo + q * 8), "r"(lo0), "r"(lo1));
        }
    }
    // W tile 64x128
    {
        int r = tid >> 2, seg = (tid & 3) * 32;
        const float4* src = (const float4*)(W_ih + (size_t)(n0 + r) * In + seg);
        uint32_t dhi = sb + XS_WHI + r * XROWB + seg * 2;
        uint32_t dlo = sb + XS_WLO + r * XROWB + seg * 2;
        #pragma unroll
        for (int q = 0; q < 8; q++) {
            float4 v = src[q];
            __nv_bfloat16 h0 = __float2bfloat16(v.x), h1 = __float2bfloat16(v.y);
            __nv_bfloat16 h2 = __float2bfloat16(v.z), h3 = __float2bfloat16(v.w);
            uint32_t hi0 = (uint32_t)__bfloat16_as_ushort(h0) | ((uint32_t)__bfloat16_as_ushort(h1) << 16);
            uint32_t hi1 = (uint32_t)__bfloat16_as_ushort(h2) | ((uint32_t)__bfloat16_as_ushort(h3) << 16);
            uint32_t lo0 = pack_bf16x2(v.x - __bfloat162float(h0), v.y - __bfloat162float(h1));
            uint32_t lo1 = pack_bf16x2(v.z - __bfloat162float(h2), v.w - __bfloat162float(h3));
            asm volatile("st.shared.v2.b32 [%0], {%1,%2};" :: "r"(dhi + q * 8), "r"(hi0), "r"(hi1));
            asm volatile("st.shared.v2.b32 [%0], {%1,%2};" :: "r"(dlo + q * 8), "r"(lo0), "r"(lo1));
        }
    }
    __syncthreads();

    const int wm = wid & 3, wn = wid >> 2;
    const int ja = lane >> 3, ra = lane & 7;
    const int gq = lane >> 2, tq = lane & 3;

    uint32_t a_off[2], w_off[2];
    #pragma unroll
    for (int mt = 0; mt < 2; mt++)
        a_off[mt] = (uint32_t)(wm * 32 + mt * 16 + (ja & 1) * 8 + ra) * XROWB + (uint32_t)(ja >> 1) * 16;
    #pragma unroll
    for (int np = 0; np < 2; np++)
        w_off[np] = (uint32_t)(wn * 32 + np * 16 + (ja >> 1) * 8 + ra) * XROWB + (uint32_t)(ja & 1) * 16;

    float c[2][4][4];
    #pragma unroll
    for (int i = 0; i < 2; i++)
        #pragma unroll
        for (int j = 0; j < 4; j++)
            #pragma unroll
            for (int q = 0; q < 4; q++) c[i][j][q] = 0.f;

    #pragma unroll
    for (int ks = 0; ks < 8; ks++) {
        uint32_t kb = (uint32_t)ks * 32;
        uint32_t ahi[2][4], alo[2][4], whi[2][4], wlo[2][4];
        #pragma unroll
        for (int mt = 0; mt < 2; mt++) {
            ldsm4(ahi[mt], sb + XS_AHI + a_off[mt] + kb);
            ldsm4(alo[mt], sb + XS_ALO + a_off[mt] + kb);
        }
        #pragma unroll
        for (int np = 0; np < 2; np++) {
            ldsm4(whi[np], sb + XS_WHI + w_off[np] + kb);
            ldsm4(wlo[np], sb + XS_WLO + w_off[np] + kb);
        }
        #pragma unroll
        for (int mt = 0; mt < 2; mt++)
            #pragma unroll
            for (int nt = 0; nt < 4; nt++) {
                int np = nt >> 1, h = (nt & 1) * 2;
                mma_bf16(c[mt][nt], ahi[mt], whi[np][h], whi[np][h + 1]);
                mma_bf16(c[mt][nt], ahi[mt], wlo[np][h], wlo[np][h + 1]);
                mma_bf16(c[mt][nt], alo[mt], whi[np][h], whi[np][h + 1]);
            }
    }

    // stage (c + bias) into smem fp32 tile [128][64], then coalesced copy-out
    __syncthreads();
    #pragma unroll
    for (int nt = 0; nt < 4; nt++) {
        int cl = wn * 32 + nt * 8 + tq * 2;   // local col
        int col = n0 + cl;
        float ba = b_ih[col] + b_hh[col];
        float bb = b_ih[col + 1] + b_hh[col + 1];
        #pragma unroll
        for (int mt = 0; mt < 2; mt++) {
            int rl = wm * 32 + mt * 16 + gq;  // local row
            asm volatile("st.shared.v2.f32 [%0], {%1,%2};"
                :: "r"(sb + rl * XSTG + cl * 4), "f"(c[mt][nt][0] + ba), "f"(c[mt][nt][1] + bb));
            asm volatile("st.shared.v2.f32 [%0], {%1,%2};"
                :: "r"(sb + (rl + 8) * XSTG + cl * 4), "f"(c[mt][nt][2] + ba), "f"(c[mt][nt][3] + bb));
        }
    }
    __syncthreads();
    for (int i = tid; i < 2048; i += 256) {
        int r = i >> 4, cc = (i & 15) * 4;
        uint32_t v0, v1, v2, v3;
        asm volatile("ld.shared.v4.b32 {%0,%1,%2,%3}, [%4];"
            : "=r"(v0), "=r"(v1), "=r"(v2), "=r"(v3) : "r"(sb + r * XSTG + cc * 4));
        uint4 v = make_uint4(v0, v1, v2, v3);
        *(uint4*)(g_xs + (size_t)(m0 + r) * Hn + n0 + cc) = v;
    }
}

// ---------------- persistent recurrence ----------------
#define ROWB 1040
#define OFF_WHI 0
#define OFF_WLO 33280
#define OFF_AHI 66560
#define OFF_ALO 99840
#define SMEM_RP 133120

__global__ __launch_bounds__(128, 1)
void rnn_persist(const float* __restrict__ W_hh) {
    extern __shared__ unsigned char smem[];
    const uint32_t sb = smem_u32(smem);
    const int tid = threadIdx.x;
    const int wid = tid >> 5, lane = tid & 31;
    const int cta_m = blockIdx.x >> 4;
    const int cta_n = blockIdx.x & 15;
    const int m0 = cta_m * 32, n0 = cta_n * 32;
    unsigned int* mybar = &g_bar8[cta_m * 32];

    for (int idx = tid; idx < 32 * 512; idx += 128) {
        int r = idx >> 9, k = idx & 511;
        float w = W_hh[(size_t)(n0 + r) * Hn + k];
        __nv_bfloat16 hi = __float2bfloat16(w);
        __nv_bfloat16 lo = __float2bfloat16(w - __bfloat162float(hi));
        *(__nv_bfloat16*)(smem + OFF_WHI + r * ROWB + k * 2) = hi;
        *(__nv_bfloat16*)(smem + OFF_WLO + r * ROWB + k * 2) = lo;
    }
    __syncthreads();

    const int wm = wid & 1, wn = wid >> 1;
    const int gq = lane >> 2, tq = lane & 3;
    const int ja = lane >> 3, ra = lane & 7;
    const int r0 = m0 + wm * 16 + gq;
    const int r1 = r0 + 8;
    const uint32_t a_off = (uint32_t)(wm * 16 + (ja & 1) * 8 + ra) * ROWB + (uint32_t)(ja >> 1) * 16;
    const uint32_t b_off = (uint32_t)(wn * 16 + (ja >> 1) * 8 + ra) * ROWB + (uint32_t)(ja & 1) * 16;
    const int col0 = n0 + wn * 16 + tq * 2;

    for (int t = 0; t < Tn; t++) {
        const int rb = t & 1, wb = rb ^ 1;
        const __nv_bfloat16* hh = g_hhi[rb];
        const __nv_bfloat16* hl = g_hlo[rb];

        #pragma unroll
        for (int kc = 0; kc < 2; kc++) {
            for (int i = tid; i < 1024; i += 128) {
                int row = i >> 5, inner = i & 31;
                uint32_t so = (uint32_t)row * ROWB + (uint32_t)kc * 512 + (uint32_t)inner * 16;
                size_t go = (size_t)(m0 + row) * Hn + kc * 256 + inner * 8;
                cpa16(sb + OFF_AHI + so, hh + go);
                cpa16(sb + OFF_ALO + so, hl + go);
            }
            CP_COMMIT();
        }

        const float* xs_t = g_xs + (size_t)t * (Bsz * Hn);
        float2 xv[2][2];
        #pragma unroll
        for (int nt = 0; nt < 2; nt++) {
            xv[nt][0] = *(const float2*)(xs_t + (size_t)r0 * Hn + col0 + nt * 8);
            xv[nt][1] = *(const float2*)(xs_t + (size_t)r1 * Hn + col0 + nt * 8);
        }

        float c[2][4];
        #pragma unroll
        for (int i = 0; i < 2; i++)
            #pragma unroll
            for (int j = 0; j < 4; j++) c[i][j] = 0.f;

        #pragma unroll
        for (int kc = 0; kc < 2; kc++) {
            if (kc == 0) { CP_WAIT(1); } else { CP_WAIT(0); }
            __syncthreads();
            #pragma unroll 4
            for (int ks = 0; ks < 16; ks++) {
                uint32_t kb = (uint32_t)(kc * 16 + ks) * 32;
                uint32_t ahi[4], alo[4], bhi[4], blo[4];
                ldsm4(ahi, sb + OFF_AHI + a_off + kb);
                ldsm4(alo, sb + OFF_ALO + a_off + kb);
                ldsm4(bhi, sb + OFF_WHI + b_off + kb);
                ldsm4(blo, sb + OFF_WLO + b_off + kb);
                mma_bf16(c[0], ahi, bhi[0], bhi[1]);
                mma_bf16(c[0], ahi, blo[0], blo[1]);
                mma_bf16(c[0], alo, bhi[0], bhi[1]);
                mma_bf16(c[1], ahi, bhi[2], bhi[3]);
                mma_bf16(c[1], ahi, blo[2], blo[3]);
                mma_bf16(c[1], alo, bhi[2], bhi[3]);
            }
        }

        __nv_bfloat16* ohh = g_hhi[wb];
        __nv_bfloat16* ohl = g_hlo[wb];
        #pragma unroll
        for (int nt = 0; nt < 2; nt++) {
            int col = col0 + nt * 8;
            #pragma unroll
            for (int hf = 0; hf < 2; hf++) {
                int row = hf ? r1 : r0;
                float s0 = tanhf(c[nt][hf * 2]     + xv[nt][hf].x);
                float s1 = tanhf(c[nt][hf * 2 + 1] + xv[nt][hf].y);
                __nv_bfloat16 h0 = __float2bfloat16(s0);
                __nv_bfloat16 h1 = __float2bfloat16(s1);
                uint32_t wh = (uint32_t)__bfloat16_as_ushort(h0) | ((uint32_t)__bfloat16_as_ushort(h1) << 16);
                uint32_t wl = pack_bf16x2(s0 - __bfloat162float(h0), s1 - __bfloat162float(h1));
                size_t off = (size_t)row * Hn + col;
                *(uint32_t*)(ohh + off) = wh;
                *(uint32_t*)(ohl + off) = wl;
                if (t == Tn - 1) *(float2*)(g_hT + off) = make_float2(s0, s1);
            }
        }

        // per-m-group barrier (16 CTAs); groups drift independently
        __syncthreads();
        if (tid == 0) {
            bar_arrive(mybar);
            unsigned int target = (unsigned int)(t + 1) * GROUP_SZ;
            while (bar_ld(mybar) < target) { }
        }
        __syncthreads();
    }
}

// ---------------- final FC ----------------
__global__ void fc_kernel(const float* __restrict__ fc_w, const float* __restrict__ fc_b,
                          float* __restrict__ out) {
    int b = blockIdx.x;
    float acc = 0.f;
    for (int k = threadIdx.x; k < Hn; k += 128)
        acc += g_hT[b * Hn + k] * fc_w[k];
    __shared__ float s[128];
    s[threadIdx.x] = acc;
    __syncthreads();
    #pragma unroll
    for (int o = 64; o > 0; o >>= 1) {
        if (threadIdx.x < o) s[threadIdx.x] += s[threadIdx.x + o];
        __syncthreads();
    }
    if (threadIdx.x == 0) out[b] = s[0] + fc_b[0];
}

extern "C" void kernel_launch(void* const* d_in, const int* in_sizes, int n_in,
                              void* d_out, int out_size) {
    const float* x    = (const float*)d_in[0];
    const float* W_ih = (const float*)d_in[1];
    const float* W_hh = (const float*)d_in[2];
    const float* b_ih = (const float*)d_in[3];
    const float* b_hh = (const float*)d_in[4];
    const float* fc_w = (const float*)d_in[5];
    const float* fc_b = (const float*)d_in[6];
    float* out = (float*)d_out;

    cudaFuncSetAttribute(xs_mma_kernel, cudaFuncAttributeMaxDynamicSharedMemorySize, SMEM_XS);
    cudaFuncSetAttribute(rnn_persist, cudaFuncAttributeMaxDynamicSharedMemorySize, SMEM_RP);

    init_kernel<<<256, 256>>>();
    dim3 gx(Hn / 64, (Tn * Bsz) / 128);
    xs_mma_kernel<<<gx, 256, SMEM_XS>>>(x, W_ih, b_ih, b_hh);
    rnn_persist<<<NCTA, 128, SMEM_RP>>>(W_hh);
    fc_kernel<<<Bsz, 128>>>(fc_w, fc_b, out);
}

// round 7
// speedup vs baseline: 4.2625x; 1.0981x over previous
#include <cuda_runtime.h>
#include <cuda_bf16.h>
#include <math.h>
#include <stdint.h>

#define Bsz 256
#define Tn  256
#define In  128
#define Hn  512
#define NCTA 128
#define GROUP_SZ 16

// ---------------- device scratch ----------------
__device__ float g_xs[(size_t)Tn * Bsz * Hn];
// swizzled h images: [buf][group mg: 8][kc: 2][row: 32][512B], 256KB per buf per array
__device__ uint4 g_ihi4[2][16384];
__device__ uint4 g_ilo4[2][16384];
__device__ float g_hT[Bsz * Hn];
__device__ unsigned int g_bar8[8 * 32];

// ---------------- helpers ----------------
__device__ __forceinline__ uint32_t smem_u32(const void* p) {
    uint32_t a;
    asm("{ .reg .u64 t; cvta.to.shared.u64 t, %1; cvt.u32.u64 %0, t; }" : "=r"(a) : "l"(p));
    return a;
}
#define MBI(addr, cnt) asm volatile("mbarrier.init.shared.b64 [%0], %1;" :: "r"(addr), "r"(cnt) : "memory")
#define MBTX(addr, bytes) asm volatile("mbarrier.arrive.expect_tx.shared.b64 _, [%0], %1;" :: "r"(addr), "r"(bytes) : "memory")
#define MBW(addr, par) do { \
    asm volatile("{\n\t.reg .pred P1;\n\tWL_%=:\n\t" \
        "mbarrier.try_wait.parity.acquire.cta.shared::cta.b64 P1, [%0], %1, 0x989680;\n\t" \
        "@P1 bra.uni WD_%=;\n\tbra.uni WL_%=;\n\tWD_%=:\n\t}" \
        :: "r"((uint32_t)(addr)), "r"((uint32_t)(par)) : "memory"); } while (0)

__device__ __forceinline__ void bulk_g2s(uint32_t dst, const void* src, uint32_t bytes, uint32_t mbar) {
    asm volatile("cp.async.bulk.shared::cta.global.mbarrier::complete_tx::bytes [%0], [%1], %2, [%3];"
        :: "r"(dst), "l"(src), "r"(bytes), "r"(mbar) : "memory");
}
__device__ __forceinline__ void ldsm4(uint32_t r[4], uint32_t addr) {
    asm volatile("ldmatrix.sync.aligned.m8n8.x4.shared.b16 {%0,%1,%2,%3}, [%4];"
                 : "=r"(r[0]), "=r"(r[1]), "=r"(r[2]), "=r"(r[3]) : "r"(addr));
}
__device__ __forceinline__ void mma_bf16(float c[4], const uint32_t a[4], uint32_t b0, uint32_t b1) {
    asm volatile("mma.sync.aligned.m16n8k16.row.col.f32.bf16.bf16.f32 "
                 "{%0,%1,%2,%3},{%4,%5,%6,%7},{%8,%9},{%0,%1,%2,%3};"
                 : "+f"(c[0]), "+f"(c[1]), "+f"(c[2]), "+f"(c[3])
                 : "r"(a[0]), "r"(a[1]), "r"(a[2]), "r"(a[3]), "r"(b0), "r"(b1));
}
__device__ __forceinline__ void bar_arrive(unsigned int* p) {
    asm volatile("red.add.release.gpu.u32 [%0], 1;" :: "l"(p) : "memory");
}
__device__ __forceinline__ uint32_t bar_ld(unsigned int* p) {
    uint32_t v;
    asm volatile("ld.acquire.gpu.u32 %0, [%1];" : "=r"(v) : "l"(p) : "memory");
    return v;
}
__device__ __forceinline__ uint32_t pack_bf16x2(float a, float b) {
    __nv_bfloat16 ha = __float2bfloat16(a), hb = __float2bfloat16(b);
    return (uint32_t)__bfloat16_as_ushort(ha) | ((uint32_t)__bfloat16_as_ushort(hb) << 16);
}

// ---------------- init ----------------
__global__ void init_kernel() {
    int i = blockIdx.x * blockDim.x + threadIdx.x;
    if (i < 8 * 32) g_bar8[i] = 0u;
    if (i < 16384) {
        g_ihi4[0][i] = make_uint4(0,0,0,0); g_ihi4[1][i] = make_uint4(0,0,0,0);
        g_ilo4[0][i] = make_uint4(0,0,0,0); g_ilo4[1][i] = make_uint4(0,0,0,0);
    }
}

// ---------------- xs GEMM via mma.sync (unchanged, proven) ----------------
#define XROWB 272
#define XS_AHI 0
#define XS_ALO 34816
#define XS_WHI 69632
#define XS_WLO 87040
#define SMEM_XS 104448
#define XSTG 272

__global__ __launch_bounds__(256, 1)
void xs_mma_kernel(const float* __restrict__ x, const float* __restrict__ W_ih,
                   const float* __restrict__ b_ih, const float* __restrict__ b_hh) {
    extern __shared__ unsigned char smem[];
    const uint32_t sb = smem_u32(smem);
    const int tid = threadIdx.x;
    const int wid = tid >> 5, lane = tid & 31;
    const int m0 = blockIdx.y * 128;
    const int n0 = blockIdx.x * 64;
    const int tt = m0 >> 8;
    const int b0 = m0 & 255;

    {
        int r = tid >> 1, seg = (tid & 1) * 64;
        const float4* src = (const float4*)(x + ((size_t)(b0 + r) * Tn + tt) * In + seg);
        uint32_t dhi = sb + XS_AHI + r * XROWB + seg * 2;
        uint32_t dlo = sb + XS_ALO + r * XROWB + seg * 2;
        #pragma unroll
        for (int q = 0; q < 16; q++) {
            float4 v = src[q];
            __nv_bfloat16 h0 = __float2bfloat16(v.x), h1 = __float2bfloat16(v.y);
            __nv_bfloat16 h2 = __float2bfloat16(v.z), h3 = __float2bfloat16(v.w);
            uint32_t hi0 = (uint32_t)__bfloat16_as_ushort(h0) | ((uint32_t)__bfloat16_as_ushort(h1) << 16);
            uint32_t hi1 = (uint32_t)__bfloat16_as_ushort(h2) | ((uint32_t)__bfloat16_as_ushort(h3) << 16);
            uint32_t lo0 = pack_bf16x2(v.x - __bfloat162float(h0), v.y - __bfloat162float(h1));
            uint32_t lo1 = pack_bf16x2(v.z - __bfloat162float(h2), v.w - __bfloat162float(h3));
            asm volatile("st.shared.v2.b32 [%0], {%1,%2};" :: "r"(dhi + q * 8), "r"(hi0), "r"(hi1));
            asm volatile("st.shared.v2.b32 [%0], {%1,%2};" :: "r"(dlo + q * 8), "r"(lo0), "r"(lo1));
        }
    }
    {
        int r = tid >> 2, seg = (tid & 3) * 32;
        const float4* src = (const float4*)(W_ih + (size_t)(n0 + r) * In + seg);
        uint32_t dhi = sb + XS_WHI + r * XROWB + seg * 2;
        uint32_t dlo = sb + XS_WLO + r * XROWB + seg * 2;
        #pragma unroll
        for (int q = 0; q < 8; q++) {
            float4 v = src[q];
            __nv_bfloat16 h0 = __float2bfloat16(v.x), h1 = __float2bfloat16(v.y);
            __nv_bfloat16 h2 = __float2bfloat16(v.z), h3 = __float2bfloat16(v.w);
            uint32_t hi0 = (uint32_t)__bfloat16_as_ushort(h0) | ((uint32_t)__bfloat16_as_ushort(h1) << 16);
            uint32_t hi1 = (uint32_t)__bfloat16_as_ushort(h2) | ((uint32_t)__bfloat16_as_ushort(h3) << 16);
            uint32_t lo0 = pack_bf16x2(v.x - __bfloat162float(h0), v.y - __bfloat162float(h1));
            uint32_t lo1 = pack_bf16x2(v.z - __bfloat162float(h2), v.w - __bfloat162float(h3));
            asm volatile("st.shared.v2.b32 [%0], {%1,%2};" :: "r"(dhi + q * 8), "r"(hi0), "r"(hi1));
            asm volatile("st.shared.v2.b32 [%0], {%1,%2};" :: "r"(dlo + q * 8), "r"(lo0), "r"(lo1));
        }
    }
    __syncthreads();

    const int wm = wid & 3, wn = wid >> 2;
    const int ja = lane >> 3, ra = lane & 7;
    const int gq = lane >> 2, tq = lane & 3;

    uint32_t a_off[2], w_off[2];
    #pragma unroll
    for (int mt = 0; mt < 2; mt++)
        a_off[mt] = (uint32_t)(wm * 32 + mt * 16 + (ja & 1) * 8 + ra) * XROWB + (uint32_t)(ja >> 1) * 16;
    #pragma unroll
    for (int np = 0; np < 2; np++)
        w_off[np] = (uint32_t)(wn * 32 + np * 16 + (ja >> 1) * 8 + ra) * XROWB + (uint32_t)(ja & 1) * 16;

    float c[2][4][4];
    #pragma unroll
    for (int i = 0; i < 2; i++)
        #pragma unroll
        for (int j = 0; j < 4; j++)
            #pragma unroll
            for (int q = 0; q < 4; q++) c[i][j][q] = 0.f;

    #pragma unroll
    for (int ks = 0; ks < 8; ks++) {
        uint32_t kb = (uint32_t)ks * 32;
        uint32_t ahi[2][4], alo[2][4], whi[2][4], wlo[2][4];
        #pragma unroll
        for (int mt = 0; mt < 2; mt++) {
            ldsm4(ahi[mt], sb + XS_AHI + a_off[mt] + kb);
            ldsm4(alo[mt], sb + XS_ALO + a_off[mt] + kb);
        }
        #pragma unroll
        for (int np = 0; np < 2; np++) {
            ldsm4(whi[np], sb + XS_WHI + w_off[np] + kb);
            ldsm4(wlo[np], sb + XS_WLO + w_off[np] + kb);
        }
        #pragma unroll
        for (int mt = 0; mt < 2; mt++)
            #pragma unroll
            for (int nt = 0; nt < 4; nt++) {
                int np = nt >> 1, h = (nt & 1) * 2;
                mma_bf16(c[mt][nt], ahi[mt], whi[np][h], whi[np][h + 1]);
                mma_bf16(c[mt][nt], ahi[mt], wlo[np][h], wlo[np][h + 1]);
                mma_bf16(c[mt][nt], alo[mt], whi[np][h], whi[np][h + 1]);
            }
    }

    __syncthreads();
    #pragma unroll
    for (int nt = 0; nt < 4; nt++) {
        int cl = wn * 32 + nt * 8 + tq * 2;
        int col = n0 + cl;
        float ba = b_ih[col] + b_hh[col];
        float bb = b_ih[col + 1] + b_hh[col + 1];
        #pragma unroll
        for (int mt = 0; mt < 2; mt++) {
            int rl = wm * 32 + mt * 16 + gq;
            asm volatile("st.shared.v2.f32 [%0], {%1,%2};"
                :: "r"(sb + rl * XSTG + cl * 4), "f"(c[mt][nt][0] + ba), "f"(c[mt][nt][1] + bb));
            asm volatile("st.shared.v2.f32 [%0], {%1,%2};"
                :: "r"(sb + (rl + 8) * XSTG + cl * 4), "f"(c[mt][nt][2] + ba), "f"(c[mt][nt][3] + bb));
        }
    }
    __syncthreads();
    for (int i = tid; i < 2048; i += 256) {
        int r = i >> 4, cc = (i & 15) * 4;
        uint32_t v0, v1, v2, v3;
        asm volatile("ld.shared.v4.b32 {%0,%1,%2,%3}, [%4];"
            : "=r"(v0), "=r"(v1), "=r"(v2), "=r"(v3) : "r"(sb + r * XSTG + cc * 4));
        *(uint4*)(g_xs + (size_t)(m0 + r) * Hn + n0 + cc) = make_uint4(v0, v1, v2, v3);
    }
}

// ---------------- persistent recurrence: bulk-copy swizzled h images ----------------
// SMEM: [0,16) mbarriers; [1024) Whi 33280; Wlo 33280; Ahi 32768; Alo 32768
#define ROWB 1040
#define OFF_BAR 0
#define OFF_WHI 1024
#define OFF_WLO 34304
#define OFF_AHI 67584
#define OFF_ALO 100352
#define SMEM_RP 133120

__global__ __launch_bounds__(128, 1)
void rnn_persist(const float* __restrict__ W_hh) {
    extern __shared__ unsigned char smem[];
    const uint32_t sb = smem_u32(smem);
    const int tid = threadIdx.x;
    const int wid = tid >> 5, lane = tid & 31;
    const int cta_m = blockIdx.x >> 4;          // m-group mg
    const int cta_n = blockIdx.x & 15;
    const int m0 = cta_m * 32, n0 = cta_n * 32;
    unsigned int* mybar = &g_bar8[cta_m * 32];

    // W tile (resident)
    for (int idx = tid; idx < 32 * 512; idx += 128) {
        int r = idx >> 9, k = idx & 511;
        float w = W_hh[(size_t)(n0 + r) * Hn + k];
        __nv_bfloat16 hi = __float2bfloat16(w);
        __nv_bfloat16 lo = __float2bfloat16(w - __bfloat162float(hi));
        *(__nv_bfloat16*)(smem + OFF_WHI + r * ROWB + k * 2) = hi;
        *(__nv_bfloat16*)(smem + OFF_WLO + r * ROWB + k * 2) = lo;
    }
    if (tid == 0) { MBI(sb + OFF_BAR, 1); MBI(sb + OFF_BAR + 8, 1); }
    __syncthreads();

    const int wm = wid & 1, wn = wid >> 1;
    const int gq = lane >> 2, tq = lane & 3;
    const int ja = lane >> 3, ra = lane & 7;
    const int r0 = m0 + wm * 16 + gq;
    const int r1 = r0 + 8;
    // A ldmatrix lane constants (swizzled 512B-row image)
    const int r_loc = wm * 16 + (ja & 1) * 8 + ra;     // 0..31
    const uint32_t a_rowbase = (uint32_t)r_loc * 512;
    const uint32_t rl = (uint32_t)(r_loc & 7);
    const uint32_t uo = (uint32_t)(ja >> 1);
    const uint32_t b_off = (uint32_t)(wn * 16 + (ja >> 1) * 8 + ra) * ROWB + (uint32_t)(ja & 1) * 16;
    const int col0 = n0 + wn * 16 + tq * 2;

    // epilogue image constants
    const int rle0 = wm * 16 + gq;                      // local rows written: rle0, rle0+8
    unsigned char* const img_hi_base = (unsigned char*)g_ihi4;
    unsigned char* const img_lo_base = (unsigned char*)g_ilo4;
    const size_t grp_off = (size_t)cta_m * 32768;

    for (int t = 0; t < Tn; t++) {
        const int rb = t & 1, wb = rb ^ 1;
        const unsigned char* shi = (const unsigned char*)g_ihi4[rb] + grp_off;
        const unsigned char* slo = (const unsigned char*)g_ilo4[rb] + grp_off;

        if (tid == 0) {
            MBTX(sb + OFF_BAR, 32768u);
            bulk_g2s(sb + OFF_AHI, shi, 16384u, sb + OFF_BAR);
            bulk_g2s(sb + OFF_ALO, slo, 16384u, sb + OFF_BAR);
            MBTX(sb + OFF_BAR + 8, 32768u);
            bulk_g2s(sb + OFF_AHI + 16384, shi + 16384, 16384u, sb + OFF_BAR + 8);
            bulk_g2s(sb + OFF_ALO + 16384, slo + 16384, 16384u, sb + OFF_BAR + 8);
        }

        const float* xs_t = g_xs + (size_t)t * (Bsz * Hn);
        float2 xv[2][2];
        #pragma unroll
        for (int nt = 0; nt < 2; nt++) {
            xv[nt][0] = *(const float2*)(xs_t + (size_t)r0 * Hn + col0 + nt * 8);
            xv[nt][1] = *(const float2*)(xs_t + (size_t)r1 * Hn + col0 + nt * 8);
        }

        float c[2][4];
        #pragma unroll
        for (int i = 0; i < 2; i++)
            #pragma unroll
            for (int j = 0; j < 4; j++) c[i][j] = 0.f;

        #pragma unroll
        for (int kc = 0; kc < 2; kc++) {
            MBW(sb + OFF_BAR + 8 * kc, t & 1);
            #pragma unroll 8
            for (int ks2 = 0; ks2 < 16; ks2++) {
                uint32_t u = ((uint32_t)ks2 << 1) | uo;
                uint32_t u2 = (u & 24u) | ((u & 7u) ^ rl);
                uint32_t aoff = ((uint32_t)kc << 14) + a_rowbase + (u2 << 4);
                uint32_t kb = (uint32_t)(kc * 16 + ks2) * 32;
                uint32_t ahi[4], alo[4], bhi[4], blo[4];
                ldsm4(ahi, sb + OFF_AHI + aoff);
                ldsm4(alo, sb + OFF_ALO + aoff);
                ldsm4(bhi, sb + OFF_WHI + b_off + kb);
                ldsm4(blo, sb + OFF_WLO + b_off + kb);
                mma_bf16(c[0], ahi, bhi[0], bhi[1]);
                mma_bf16(c[0], ahi, blo[0], blo[1]);
                mma_bf16(c[0], alo, bhi[0], bhi[1]);
                mma_bf16(c[1], ahi, bhi[2], bhi[3]);
                mma_bf16(c[1], ahi, blo[2], blo[3]);
                mma_bf16(c[1], alo, bhi[2], bhi[3]);
            }
        }

        // epilogue: tanh(c + xs), write swizzled bf16 hi/lo image for buf wb
        unsigned char* ohi = img_hi_base + (size_t)wb * 262144 + grp_off;
        unsigned char* olo = img_lo_base + (size_t)wb * 262144 + grp_off;
        #pragma unroll
        for (int nt = 0; nt < 2; nt++) {
            int col = col0 + nt * 8;
            int kc = col >> 8;
            uint32_t u = (uint32_t)((col & 255) >> 3);
            #pragma unroll
            for (int hf = 0; hf < 2; hf++) {
                int rle = rle0 + hf * 8;
                float s0 = tanhf(c[nt][hf * 2]     + xv[nt][hf].x);
                float s1 = tanhf(c[nt][hf * 2 + 1] + xv[nt][hf].y);
                __nv_bfloat16 h0 = __float2bfloat16(s0);
                __nv_bfloat16 h1 = __float2bfloat16(s1);
                uint32_t wh = (uint32_t)__bfloat16_as_ushort(h0) | ((uint32_t)__bfloat16_as_ushort(h1) << 16);
                uint32_t wl = pack_bf16x2(s0 - __bfloat162float(h0), s1 - __bfloat162float(h1));
                uint32_t u2 = (u & 24u) | ((u & 7u) ^ (uint32_t)(rle & 7));
                uint32_t off = (uint32_t)kc * 16384u + (uint32_t)rle * 512u + (u2 << 4) + (uint32_t)(tq * 4);
                *(uint32_t*)(ohi + off) = wh;
                *(uint32_t*)(olo + off) = wl;
                if (t == Tn - 1)
                    *(float2*)(g_hT + (size_t)(m0 + rle) * Hn + col) = make_float2(s0, s1);
            }
        }

        // per-m-group barrier
        __syncthreads();
        if (tid == 0) {
            bar_arrive(mybar);
            unsigned int target = (unsigned int)(t + 1) * GROUP_SZ;
            while (bar_ld(mybar) < target) { }
        }
        __syncthreads();
    }
}

// ---------------- final FC ----------------
__global__ void fc_kernel(const float* __restrict__ fc_w, const float* __restrict__ fc_b,
                          float* __restrict__ out) {
    int b = blockIdx.x;
    float acc = 0.f;
    for (int k = threadIdx.x; k < Hn; k += 128)
        acc += g_hT[b * Hn + k] * fc_w[k];
    __shared__ float s[128];
    s[threadIdx.x] = acc;
    __syncthreads();
    #pragma unroll
    for (int o = 64; o > 0; o >>= 1) {
        if (threadIdx.x < o) s[threadIdx.x] += s[threadIdx.x + o];
        __syncthreads();
    }
    if (threadIdx.x == 0) out[b] = s[0] + fc_b[0];
}

extern "C" void kernel_launch(void* const* d_in, const int* in_sizes, int n_in,
                              void* d_out, int out_size) {
    const float* x    = (const float*)d_in[0];
    const float* W_ih = (const float*)d_in[1];
    const float* W_hh = (const float*)d_in[2];
    const float* b_ih = (const float*)d_in[3];
    const float* b_hh = (const float*)d_in[4];
    const float* fc_w = (const float*)d_in[5];
    const float* fc_b = (const float*)d_in[6];
    float* out = (float*)d_out;

    cudaFuncSetAttribute(xs_mma_kernel, cudaFuncAttributeMaxDynamicSharedMemorySize, SMEM_XS);
    cudaFuncSetAttribute(rnn_persist, cudaFuncAttributeMaxDynamicSharedMemorySize, SMEM_RP);

    init_kernel<<<256, 256>>>();
    dim3 gx(Hn / 64, (Tn * Bsz) / 128);
    xs_mma_kernel<<<gx, 256, SMEM_XS>>>(x, W_ih, b_ih, b_hh);
    rnn_persist<<<NCTA, 128, SMEM_RP>>>(W_hh);
    fc_kernel<<<Bsz, 128>>>(fc_w, fc_b, out);
}

// round 8
// speedup vs baseline: 4.4268x; 1.0385x over previous
#include <cuda_runtime.h>
#include <cuda_bf16.h>
#include <math.h>
#include <stdint.h>

#define Bsz 256
#define Tn  256
#define In  128
#define Hn  512
#define NCTA 128
#define GROUP_SZ 16

// ---------------- device scratch ----------------
__device__ float g_xs[(size_t)Tn * Bsz * Hn];
// swizzled h images: [buf][group mg: 8][kc: 2][row: 32][512B]
__device__ uint4 g_ihi4[2][16384];
__device__ uint4 g_ilo4[2][16384];
__device__ float g_hT[Bsz * Hn];
__device__ unsigned int g_barA[8 * 32];   // kc0 producers (n<8), padded
__device__ unsigned int g_barB[8 * 32];   // kc1 producers (n>=8)

// ---------------- helpers ----------------
__device__ __forceinline__ uint32_t smem_u32(const void* p) {
    uint32_t a;
    asm("{ .reg .u64 t; cvta.to.shared.u64 t, %1; cvt.u32.u64 %0, t; }" : "=r"(a) : "l"(p));
    return a;
}
#define MBI(addr, cnt) asm volatile("mbarrier.init.shared.b64 [%0], %1;" :: "r"(addr), "r"(cnt) : "memory")
#define MBTX(addr, bytes) asm volatile("mbarrier.arrive.expect_tx.shared.b64 _, [%0], %1;" :: "r"(addr), "r"(bytes) : "memory")
#define MBW(addr, par) do { \
    asm volatile("{\n\t.reg .pred P1;\n\tWL_%=:\n\t" \
        "mbarrier.try_wait.parity.acquire.cta.shared::cta.b64 P1, [%0], %1, 0x989680;\n\t" \
        "@P1 bra.uni WD_%=;\n\tbra.uni WL_%=;\n\tWD_%=:\n\t}" \
        :: "r"((uint32_t)(addr)), "r"((uint32_t)(par)) : "memory"); } while (0)

__device__ __forceinline__ void bulk_g2s(uint32_t dst, const void* src, uint32_t bytes, uint32_t mbar) {
    asm volatile("cp.async.bulk.shared::cta.global.mbarrier::complete_tx::bytes [%0], [%1], %2, [%3];"
        :: "r"(dst), "l"(src), "r"(bytes), "r"(mbar) : "memory");
}
__device__ __forceinline__ void ldsm4(uint32_t r[4], uint32_t addr) {
    asm volatile("ldmatrix.sync.aligned.m8n8.x4.shared.b16 {%0,%1,%2,%3}, [%4];"
                 : "=r"(r[0]), "=r"(r[1]), "=r"(r[2]), "=r"(r[3]) : "r"(addr));
}
__device__ __forceinline__ void mma_bf16(float c[4], const uint32_t a[4], uint32_t b0, uint32_t b1) {
    asm volatile("mma.sync.aligned.m16n8k16.row.col.f32.bf16.bf16.f32 "
                 "{%0,%1,%2,%3},{%4,%5,%6,%7},{%8,%9},{%0,%1,%2,%3};"
                 : "+f"(c[0]), "+f"(c[1]), "+f"(c[2]), "+f"(c[3])
                 : "r"(a[0]), "r"(a[1]), "r"(a[2]), "r"(a[3]), "r"(b0), "r"(b1));
}
__device__ __forceinline__ void bar_arrive(unsigned int* p) {
    asm volatile("red.add.release.gpu.u32 [%0], 1;" :: "l"(p) : "memory");
}
__device__ __forceinline__ uint32_t bar_ld(unsigned int* p) {
    uint32_t v;
    asm volatile("ld.acquire.gpu.u32 %0, [%1];" : "=r"(v) : "l"(p) : "memory");
    return v;
}
__device__ __forceinline__ uint32_t pack_bf16x2(float a, float b) {
    __nv_bfloat16 ha = __float2bfloat16(a), hb = __float2bfloat16(b);
    return (uint32_t)__bfloat16_as_ushort(ha) | ((uint32_t)__bfloat16_as_ushort(hb) << 16);
}

// ---------------- init ----------------
__global__ void init_kernel() {
    int i = blockIdx.x * blockDim.x + threadIdx.x;
    if (i < 8 * 32) { g_barA[i] = 0u; g_barB[i] = 0u; }
    if (i < 16384) {
        g_ihi4[0][i] = make_uint4(0,0,0,0); g_ihi4[1][i] = make_uint4(0,0,0,0);
        g_ilo4[0][i] = make_uint4(0,0,0,0); g_ilo4[1][i] = make_uint4(0,0,0,0);
    }
}

// ---------------- xs GEMM: m64 x n64 tiles, 2 CTAs/SM ----------------
#define X2ROWB 272
#define X2_AHI 0
#define X2_ALO 17408
#define X2_WHI 34816
#define X2_WLO 52224
#define SMEM_X2 69632

__global__ __launch_bounds__(256, 2)
void xs_mma_kernel(const float* __restrict__ x, const float* __restrict__ W_ih,
                   const float* __restrict__ b_ih, const float* __restrict__ b_hh) {
    extern __shared__ unsigned char smem[];
    const uint32_t sb = smem_u32(smem);
    const int tid = threadIdx.x;
    const int wid = tid >> 5, lane = tid & 31;
    const int m0 = blockIdx.y * 64;
    const int n0 = blockIdx.x * 64;
    const int tt = m0 >> 8;
    const int b0 = m0 & 255;

    // A tile 64x128 fp32 -> bf16 hi/lo (4 threads per row)
    {
        int r = tid >> 2, seg = (tid & 3) * 32;
        const float4* src = (const float4*)(x + ((size_t)(b0 + r) * Tn + tt) * In + seg);
        uint32_t dhi = sb + X2_AHI + r * X2ROWB + seg * 2;
        uint32_t dlo = sb + X2_ALO + r * X2ROWB + seg * 2;
        #pragma unroll
        for (int q = 0; q < 8; q++) {
            float4 v = src[q];
            __nv_bfloat16 h0 = __float2bfloat16(v.x), h1 = __float2bfloat16(v.y);
            __nv_bfloat16 h2 = __float2bfloat16(v.z), h3 = __float2bfloat16(v.w);
            uint32_t hi0 = (uint32_t)__bfloat16_as_ushort(h0) | ((uint32_t)__bfloat16_as_ushort(h1) << 16);
            uint32_t hi1 = (uint32_t)__bfloat16_as_ushort(h2) | ((uint32_t)__bfloat16_as_ushort(h3) << 16);
            uint32_t lo0 = pack_bf16x2(v.x - __bfloat162float(h0), v.y - __bfloat162float(h1));
            uint32_t lo1 = pack_bf16x2(v.z - __bfloat162float(h2), v.w - __bfloat162float(h3));
            asm volatile("st.shared.v2.b32 [%0], {%1,%2};" :: "r"(dhi + q * 8), "r"(hi0), "r"(hi1));
            asm volatile("st.shared.v2.b32 [%0], {%1,%2};" :: "r"(dlo + q * 8), "r"(lo0), "r"(lo1));
        }
    }
    // W tile 64x128
    {
        int r = tid >> 2, seg = (tid & 3) * 32;
        const float4* src = (const float4*)(W_ih + (size_t)(n0 + r) * In + seg);
        uint32_t dhi = sb + X2_WHI + r * X2ROWB + seg * 2;
        uint32_t dlo = sb + X2_WLO + r * X2ROWB + seg * 2;
        #pragma unroll
        for (int q = 0; q < 8; q++) {
            float4 v = src[q];
            __nv_bfloat16 h0 = __float2bfloat16(v.x), h1 = __float2bfloat16(v.y);
            __nv_bfloat16 h2 = __float2bfloat16(v.z), h3 = __float2bfloat16(v.w);
            uint32_t hi0 = (uint32_t)__bfloat16_as_ushort(h0) | ((uint32_t)__bfloat16_as_ushort(h1) << 16);
            uint32_t hi1 = (uint32_t)__bfloat16_as_ushort(h2) | ((uint32_t)__bfloat16_as_ushort(h3) << 16);
            uint32_t lo0 = pack_bf16x2(v.x - __bfloat162float(h0), v.y - __bfloat162float(h1));
            uint32_t lo1 = pack_bf16x2(v.z - __bfloat162float(h2), v.w - __bfloat162float(h3));
            asm volatile("st.shared.v2.b32 [%0], {%1,%2};" :: "r"(dhi + q * 8), "r"(hi0), "r"(hi1));
            asm volatile("st.shared.v2.b32 [%0], {%1,%2};" :: "r"(dlo + q * 8), "r"(lo0), "r"(lo1));
        }
    }
    __syncthreads();

    const int wm = wid & 3, wn = wid >> 2;    // warp tile m16 x n32
    const int ja = lane >> 3, ra = lane & 7;
    const int gq = lane >> 2, tq = lane & 3;

    const uint32_t a_off = (uint32_t)(wm * 16 + (ja & 1) * 8 + ra) * X2ROWB + (uint32_t)(ja >> 1) * 16;
    uint32_t w_off[2];
    #pragma unroll
    for (int np = 0; np < 2; np++)
        w_off[np] = (uint32_t)(wn * 32 + np * 16 + (ja >> 1) * 8 + ra) * X2ROWB + (uint32_t)(ja & 1) * 16;

    float c[4][4];
    #pragma unroll
    for (int j = 0; j < 4; j++)
        #pragma unroll
        for (int q = 0; q < 4; q++) c[j][q] = 0.f;

    #pragma unroll
    for (int ks = 0; ks < 8; ks++) {
        uint32_t kb = (uint32_t)ks * 32;
        uint32_t ahi[4], alo[4], whi[2][4], wlo[2][4];
        ldsm4(ahi, sb + X2_AHI + a_off + kb);
        ldsm4(alo, sb + X2_ALO + a_off + kb);
        #pragma unroll
        for (int np = 0; np < 2; np++) {
            ldsm4(whi[np], sb + X2_WHI + w_off[np] + kb);
            ldsm4(wlo[np], sb + X2_WLO + w_off[np] + kb);
        }
        #pragma unroll
        for (int nt = 0; nt < 4; nt++) {
            int np = nt >> 1, h = (nt & 1) * 2;
            mma_bf16(c[nt], ahi, whi[np][h], whi[np][h + 1]);
            mma_bf16(c[nt], ahi, wlo[np][h], wlo[np][h + 1]);
            mma_bf16(c[nt], alo, whi[np][h], whi[np][h + 1]);
        }
    }

    // stage (c + bias) in smem (reuse A region), then coalesced copy-out
    __syncthreads();
    #pragma unroll
    for (int nt = 0; nt < 4; nt++) {
        int cl = wn * 32 + nt * 8 + tq * 2;
        int col = n0 + cl;
        float ba = b_ih[col] + b_hh[col];
        float bb = b_ih[col + 1] + b_hh[col + 1];
        int rl = wm * 16 + gq;
        asm volatile("st.shared.v2.f32 [%0], {%1,%2};"
            :: "r"(sb + rl * X2ROWB + cl * 4), "f"(c[nt][0] + ba), "f"(c[nt][1] + bb));
        asm volatile("st.shared.v2.f32 [%0], {%1,%2};"
            :: "r"(sb + (rl + 8) * X2ROWB + cl * 4), "f"(c[nt][2] + ba), "f"(c[nt][3] + bb));
    }
    __syncthreads();
    for (int i = tid; i < 1024; i += 256) {
        int r = i >> 4, cc = (i & 15) * 4;
        uint32_t v0, v1, v2, v3;
        asm volatile("ld.shared.v4.b32 {%0,%1,%2,%3}, [%4];"
            : "=r"(v0), "=r"(v1), "=r"(v2), "=r"(v3) : "r"(sb + r * X2ROWB + cc * 4));
        *(uint4*)(g_xs + (size_t)(m0 + r) * Hn + n0 + cc) = make_uint4(v0, v1, v2, v3);
    }
}

// ---------------- persistent recurrence: split-kc barriers + DMA warp ----------------
#define ROWB 1040
#define OFF_BAR 0          // sigA @0, sigB @8
#define OFF_WHI 1024
#define OFF_WLO 34304
#define OFF_AHI 67584
#define OFF_ALO 100352
#define SMEM_RP 133120

__global__ __launch_bounds__(160, 1)
void rnn_persist(const float* __restrict__ W_hh) {
    extern __shared__ unsigned char smem[];
    const uint32_t sb = smem_u32(smem);
    const int tid = threadIdx.x;
    const int wid = tid >> 5, lane = tid & 31;
    const int cta_m = blockIdx.x >> 4;
    const int cta_n = blockIdx.x & 15;
    const int m0 = cta_m * 32, n0 = cta_n * 32;
    unsigned int* bar_out = (cta_n < 8) ? &g_barA[cta_m * 32] : &g_barB[cta_m * 32];
    unsigned int* barA = &g_barA[cta_m * 32];
    unsigned int* barB = &g_barB[cta_m * 32];

    // W tile (resident), loaded by all 160 threads
    for (int idx = tid; idx < 32 * 512; idx += 160) {
        int r = idx / 512, k = idx & 511;
        float w = W_hh[(size_t)(n0 + r) * Hn + k];
        __nv_bfloat16 hi = __float2bfloat16(w);
        __nv_bfloat16 lo = __float2bfloat16(w - __bfloat162float(hi));
        *(__nv_bfloat16*)(smem + OFF_WHI + r * ROWB + k * 2) = hi;
        *(__nv_bfloat16*)(smem + OFF_WLO + r * ROWB + k * 2) = lo;
    }
    if (tid == 0) { MBI(sb + OFF_BAR, 1); MBI(sb + OFF_BAR + 8, 1); }
    __syncthreads();

    // MMA-warp lane constants
    const int wm = wid & 1, wn = wid >> 1;
    const int gq = lane >> 2, tq = lane & 3;
    const int ja = lane >> 3, ra = lane & 7;
    const int r0 = m0 + wm * 16 + gq;
    const int r1 = r0 + 8;
    const int r_loc = wm * 16 + (ja & 1) * 8 + ra;
    const uint32_t a_rowbase = (uint32_t)r_loc * 512;
    const uint32_t rl = (uint32_t)(r_loc & 7);
    const uint32_t uo = (uint32_t)(ja >> 1);
    const uint32_t b_off = (uint32_t)(wn * 16 + (ja >> 1) * 8 + ra) * ROWB + (uint32_t)(ja & 1) * 16;
    const int col0 = n0 + wn * 16 + tq * 2;
    const int rle0 = wm * 16 + gq;
    unsigned char* const img_hi_base = (unsigned char*)g_ihi4;
    unsigned char* const img_lo_base = (unsigned char*)g_ilo4;
    const size_t grp_off = (size_t)cta_m * 32768;

    for (int t = 0; t < Tn; t++) {
        const int rb = t & 1, wb = rb ^ 1;

        if (wid == 4) {
            if (lane == 0) {
                const unsigned char* shi = (const unsigned char*)g_ihi4[rb] + grp_off;
                const unsigned char* slo = (const unsigned char*)g_ilo4[rb] + grp_off;
                unsigned int target = (unsigned int)t * 8u;
                if (t > 0) {
                    bar_arrive(bar_out);             // completion of step t-1
                    while (bar_ld(barA) < target) { }
                }
                MBTX(sb + OFF_BAR, 32768u);
                bulk_g2s(sb + OFF_AHI, shi, 16384u, sb + OFF_BAR);
                bulk_g2s(sb + OFF_ALO, slo, 16384u, sb + OFF_BAR);
                if (t > 0) { while (bar_ld(barB) < target) { } }
                MBTX(sb + OFF_BAR + 8, 32768u);
                bulk_g2s(sb + OFF_AHI + 16384, shi + 16384, 16384u, sb + OFF_BAR + 8);
                bulk_g2s(sb + OFF_ALO + 16384, slo + 16384, 16384u, sb + OFF_BAR + 8);
            }
        } else {
            const float* xs_t = g_xs + (size_t)t * (Bsz * Hn);
            float2 xv[2][2];
            #pragma unroll
            for (int nt = 0; nt < 2; nt++) {
                xv[nt][0] = *(const float2*)(xs_t + (size_t)r0 * Hn + col0 + nt * 8);
                xv[nt][1] = *(const float2*)(xs_t + (size_t)r1 * Hn + col0 + nt * 8);
            }

            float c[2][4];
            #pragma unroll
            for (int i = 0; i < 2; i++)
                #pragma unroll
                for (int j = 0; j < 4; j++) c[i][j] = 0.f;

            #pragma unroll
            for (int kc = 0; kc < 2; kc++) {
                MBW(sb + OFF_BAR + 8 * kc, t & 1);
                #pragma unroll 8
                for (int ks2 = 0; ks2 < 16; ks2++) {
                    uint32_t u = ((uint32_t)ks2 << 1) | uo;
                    uint32_t u2 = (u & 24u) | ((u & 7u) ^ rl);
                    uint32_t aoff = ((uint32_t)kc << 14) + a_rowbase + (u2 << 4);
                    uint32_t kb = (uint32_t)(kc * 16 + ks2) * 32;
                    uint32_t ahi[4], alo[4], bhi[4], blo[4];
                    ldsm4(ahi, sb + OFF_AHI + aoff);
                    ldsm4(alo, sb + OFF_ALO + aoff);
                    ldsm4(bhi, sb + OFF_WHI + b_off + kb);
                    ldsm4(blo, sb + OFF_WLO + b_off + kb);
                    mma_bf16(c[0], ahi, bhi[0], bhi[1]);
                    mma_bf16(c[0], ahi, blo[0], blo[1]);
                    mma_bf16(c[0], alo, bhi[0], bhi[1]);
                    mma_bf16(c[1], ahi, bhi[2], bhi[3]);
                    mma_bf16(c[1], ahi, blo[2], blo[3]);
                    mma_bf16(c[1], alo, bhi[2], bhi[3]);
                }
            }

            unsigned char* ohi = img_hi_base + (size_t)wb * 262144 + grp_off;
            unsigned char* olo = img_lo_base + (size_t)wb * 262144 + grp_off;
            #pragma unroll
            for (int nt = 0; nt < 2; nt++) {
                int col = col0 + nt * 8;
                int kc = col >> 8;
                uint32_t u = (uint32_t)((col & 255) >> 3);
                #pragma unroll
                for (int hf = 0; hf < 2; hf++) {
                    int rle = rle0 + hf * 8;
                    float s0 = tanhf(c[nt][hf * 2]     + xv[nt][hf].x);
                    float s1 = tanhf(c[nt][hf * 2 + 1] + xv[nt][hf].y);
                    __nv_bfloat16 h0 = __float2bfloat16(s0);
                    __nv_bfloat16 h1 = __float2bfloat16(s1);
                    uint32_t wh = (uint32_t)__bfloat16_as_ushort(h0) | ((uint32_t)__bfloat16_as_ushort(h1) << 16);
                    uint32_t wl = pack_bf16x2(s0 - __bfloat162float(h0), s1 - __bfloat162float(h1));
                    uint32_t u2 = (u & 24u) | ((u & 7u) ^ (uint32_t)(rle & 7));
                    uint32_t off = (uint32_t)kc * 16384u + (uint32_t)rle * 512u + (u2 << 4) + (uint32_t)(tq * 4);
                    *(uint32_t*)(ohi + off) = wh;
                    *(uint32_t*)(olo + off) = wl;
                    if (t == Tn - 1)
                        *(float2*)(g_hT + (size_t)(m0 + rle) * Hn + col) = make_float2(s0, s1);
                }
            }
        }
        __syncthreads();
    }
}

// ---------------- final FC ----------------
__global__ void fc_kernel(const float* __restrict__ fc_w, const float* __restrict__ fc_b,
                          float* __restrict__ out) {
    int b = blockIdx.x;
    float acc = 0.f;
    for (int k = threadIdx.x; k < Hn; k += 128)
        acc += g_hT[b * Hn + k] * fc_w[k];
    __shared__ float s[128];
    s[threadIdx.x] = acc;
    __syncthreads();
    #pragma unroll
    for (int o = 64; o > 0; o >>= 1) {
        if (threadIdx.x < o) s[threadIdx.x] += s[threadIdx.x + o];
        __syncthreads();
    }
    if (threadIdx.x == 0) out[b] = s[0] + fc_b[0];
}

extern "C" void kernel_launch(void* const* d_in, const int* in_sizes, int n_in,
                              void* d_out, int out_size) {
    const float* x    = (const float*)d_in[0];
    const float* W_ih = (const float*)d_in[1];
    const float* W_hh = (const float*)d_in[2];
    const float* b_ih = (const float*)d_in[3];
    const float* b_hh = (const float*)d_in[4];
    const float* fc_w = (const float*)d_in[5];
    const float* fc_b = (const float*)d_in[6];
    float* out = (float*)d_out;

    cudaFuncSetAttribute(xs_mma_kernel, cudaFuncAttributeMaxDynamicSharedMemorySize, SMEM_X2);
    cudaFuncSetAttribute(rnn_persist, cudaFuncAttributeMaxDynamicSharedMemorySize, SMEM_RP);

    init_kernel<<<256, 256>>>();
    dim3 gx(Hn / 64, (Tn * Bsz) / 64);   // (8, 1024)
    xs_mma_kernel<<<gx, 256, SMEM_X2>>>(x, W_ih, b_ih, b_hh);
    rnn_persist<<<NCTA, 160, SMEM_RP>>>(W_hh);
    fc_kernel<<<Bsz, 128>>>(fc_w, fc_b, out);
}